// round 12
// baseline (speedup 1.0000x reference)
#include <cuda_runtime.h>
#include <cuda_fp16.h>

#define S_LEN 2048
#define BSZ   2
#define EMB   1024
#define NH    16
#define DH    64
#define MROWS 4096
#define NHEADS 32
#define S2 ((long)S_LEN*S_LEN)
#define LOG2E 1.4426950408889634f

// Scratch (__device__ globals per alloc-free rule)
__device__ float g_Qp[MROWS*EMB];   // column-pair-permuted, RNA tf32 bits (pre-scaled by 0.125*log2e)
__device__ float g_Kp[MROWS*EMB];   // column-pair-permuted, RNA tf32 bits
__device__ float g_Vp[MROWS*EMB];   // normal layout, fp32
__device__ __half g_Vh[(size_t)MROWS*EMB];  // transposed fp16: row (hb*64+d), col s
__device__ float g_O [MROWS*EMB];
__device__ float g_m [NHEADS*S_LEN];   // log2-domain running max
__device__ float g_l [NHEADS*S_LEN];   // linear sum of exp2(s - m)

__device__ __forceinline__ unsigned f2tf(float f){
    unsigned u; asm("cvt.rna.tf32.f32 %0, %1;" : "=r"(u) : "f"(f)); return u;
}
__device__ __forceinline__ unsigned packh2(float lo, float hi){
    __half2 h = __floats2half2_rn(lo, hi);
    return *(unsigned*)&h;
}
__device__ __forceinline__ void mma8(float* c, const unsigned* a, const unsigned* b){
    asm volatile("mma.sync.aligned.m16n8k8.row.col.f32.tf32.tf32.f32 "
      "{%0,%1,%2,%3}, {%4,%5,%6,%7}, {%8,%9}, {%0,%1,%2,%3};\n"
      : "+f"(c[0]), "+f"(c[1]), "+f"(c[2]), "+f"(c[3])
      : "r"(a[0]), "r"(a[1]), "r"(a[2]), "r"(a[3]), "r"(b[0]), "r"(b[1]));
}
__device__ __forceinline__ void mma16f16(float* c, const unsigned* a, unsigned b0, unsigned b1){
    asm volatile("mma.sync.aligned.m16n8k16.row.col.f32.f16.f16.f32 "
      "{%0,%1,%2,%3}, {%4,%5,%6,%7}, {%8,%9}, {%0,%1,%2,%3};\n"
      : "+f"(c[0]), "+f"(c[1]), "+f"(c[2]), "+f"(c[3])
      : "r"(a[0]), "r"(a[1]), "r"(a[2]), "r"(a[3]), "r"(b0), "r"(b1));
}
__device__ __forceinline__ void cpa16(void* dst, const void* src){
    unsigned d = (unsigned)__cvta_generic_to_shared(dst);
    asm volatile("cp.async.cg.shared.global [%0], [%1], 16;\n" :: "r"(d), "l"(src));
}

// ---------------------------------------------------------------------------
// TN tf32 GEMM body (round-8 proven structure). permOut: C written
// column-pair-permuted AND as RNA tf32 bits for flash/avg consumers.
// ---------------------------------------------------------------------------
template<int BM,int BN,int BK,int WM,int WN,int NWARPS>
__device__ __forceinline__
void gemm_body(const float* __restrict__ A, int lda,
               const float* __restrict__ B, int ldb,
               float* __restrict__ C, int ldc,
               const float* __restrict__ bias, float scale, int K,
               int m0, int n0, bool permOut)
{
    constexpr int NT  = NWARPS*32;
    constexpr int LA  = BM*BK/(NT*4);
    constexpr int LB  = BN*BK/(NT*4);
    constexpr int WGN = BN/WN;
    constexpr int MI  = WM/16, NI = WN/8;
    constexpr int LDS_ = BK + 4;

    __shared__ unsigned As[2][BM][LDS_];
    __shared__ unsigned Bs[2][BN][LDS_];

    const int tid  = threadIdx.x;
    const int lane = tid & 31, wid = tid >> 5;
    const int wm = wid / WGN, wn = wid % WGN;

    float acc[MI][NI][4] = {};
    float4 ra[LA], rb[LB];

    auto ldtiles = [&](int k0){
        #pragma unroll
        for (int i = 0; i < LA; ++i){
            int idx = tid + i*NT;
            int r = idx / (BK/4), c = (idx % (BK/4)) * 4;
            ra[i] = *(const float4*)(A + (long)(m0+r)*lda + k0 + c);
        }
        #pragma unroll
        for (int i = 0; i < LB; ++i){
            int idx = tid + i*NT;
            int r = idx / (BK/4), c = (idx % (BK/4)) * 4;
            rb[i] = *(const float4*)(B + (long)(n0+r)*ldb + k0 + c);
        }
    };
    auto sttiles = [&](int buf){
        #pragma unroll
        for (int i = 0; i < LA; ++i){
            int idx = tid + i*NT;
            int r = idx / (BK/4), c = (idx % (BK/4)) * 4;
            uint4 u = { f2tf(ra[i].x), f2tf(ra[i].y), f2tf(ra[i].z), f2tf(ra[i].w) };
            *(uint4*)&As[buf][r][c] = u;
        }
        #pragma unroll
        for (int i = 0; i < LB; ++i){
            int idx = tid + i*NT;
            int r = idx / (BK/4), c = (idx % (BK/4)) * 4;
            uint4 u = { f2tf(rb[i].x), f2tf(rb[i].y), f2tf(rb[i].z), f2tf(rb[i].w) };
            *(uint4*)&Bs[buf][r][c] = u;
        }
    };
    auto compute = [&](int buf){
        #pragma unroll
        for (int ks = 0; ks < BK/8; ++ks){
            unsigned af[MI][4], bf[NI][2];
            #pragma unroll
            for (int mi = 0; mi < MI; ++mi){
                int m = wm*WM + mi*16 + (lane>>2);
                int k = ks*8 + (lane&3);
                af[mi][0] = As[buf][m  ][k  ];
                af[mi][1] = As[buf][m+8][k  ];
                af[mi][2] = As[buf][m  ][k+4];
                af[mi][3] = As[buf][m+8][k+4];
            }
            #pragma unroll
            for (int ni = 0; ni < NI; ++ni){
                int n = wn*WN + ni*8 + (lane>>2);
                int k = ks*8 + (lane&3);
                bf[ni][0] = Bs[buf][n][k  ];
                bf[ni][1] = Bs[buf][n][k+4];
            }
            #pragma unroll
            for (int mi = 0; mi < MI; ++mi)
                #pragma unroll
                for (int ni = 0; ni < NI; ++ni)
                    mma8(acc[mi][ni], af[mi], bf[ni]);
        }
    };

    ldtiles(0); sttiles(0); __syncthreads();
    const int nk = K/BK;
    for (int t = 1; t < nk; ++t){
        ldtiles(t*BK);
        compute((t-1)&1);
        sttiles(t&1);
        __syncthreads();
    }
    compute((nk-1)&1);

    #pragma unroll
    for (int mi = 0; mi < MI; ++mi){
        #pragma unroll
        for (int ni = 0; ni < NI; ++ni){
            int m = m0 + wm*WM + mi*16 + (lane>>2);
            int n = n0 + wn*WN + ni*8 + 2*(lane&3);
            float v0 = acc[mi][ni][0], v1 = acc[mi][ni][1];
            float v2 = acc[mi][ni][2], v3 = acc[mi][ni][3];
            float b0 = bias[n], b1 = bias[n+1];
            v0 = (v0+b0)*scale; v1 = (v1+b1)*scale;
            v2 = (v2+b0)*scale; v3 = (v3+b1)*scale;
            if (permOut){
                int p0 = (n & ~7) | ((n&3)<<1) | ((n>>2)&1);
                C[(long)m    *ldc + p0    ] = __uint_as_float(f2tf(v0));
                C[(long)m    *ldc + p0 + 2] = __uint_as_float(f2tf(v1));
                C[(long)(m+8)*ldc + p0    ] = __uint_as_float(f2tf(v2));
                C[(long)(m+8)*ldc + p0 + 2] = __uint_as_float(f2tf(v3));
            } else {
                *(float2*)(C + (long)m    *ldc + n) = make_float2(v0, v1);
                *(float2*)(C + (long)(m+8)*ldc + n) = make_float2(v2, v3);
            }
        }
    }
}

// Merged Q/K/V projections. Q scaled by 0.125*log2e (log2-domain scores).
__global__ __launch_bounds__(256)
void qkv_proj(const float* __restrict__ q, const float* __restrict__ k, const float* __restrict__ v,
              const float* __restrict__ qw, const float* __restrict__ qb,
              const float* __restrict__ kw, const float* __restrict__ kb,
              const float* __restrict__ vw, const float* __restrict__ vb,
              float* __restrict__ qp, float* __restrict__ kp, float* __restrict__ vp)
{
    const int z = blockIdx.z;
    const float* A  = (z==0)? q  : (z==1)? k  : v;
    const float* W  = (z==0)? qw : (z==1)? kw : vw;
    const float* bi = (z==0)? qb : (z==1)? kb : vb;
    float*       C  = (z==0)? qp : (z==1)? kp : vp;
    const float scale = (z==0)? 0.125f*LOG2E : 1.0f;
    gemm_body<64,128,16,32,32,8>(A, EMB, W, EMB, C, EMB, bi, scale, EMB,
                                 blockIdx.y*64, blockIdx.x*128, z<2);
}

__global__ __launch_bounds__(256)
void out_proj(const float* __restrict__ A, const float* __restrict__ W,
              const float* __restrict__ bi, float* __restrict__ C)
{
    gemm_body<64,128,16,32,32,8>(A, EMB, W, EMB, C, EMB, bi, 1.0f, EMB,
                                 blockIdx.y*64, blockIdx.x*128, false);
}

// ---------------------------------------------------------------------------
// V transpose+convert: vp fp32 -> vh half [hb*64+d][s].
// ---------------------------------------------------------------------------
__global__ __launch_bounds__(256)
void v_transpose(const float* __restrict__ vp, unsigned* __restrict__ vh2)
{
    __shared__ float T[64][65];
    const int tid = threadIdx.x;
    const int hb = blockIdx.y, h = hb&15, b = hb>>4;
    const int s0 = blockIdx.x*64;

    #pragma unroll
    for (int i = 0; i < 4; ++i){
        int idx = tid + i*256;
        int si = idx>>4, d4 = (idx&15)*4;
        float4 u = *(const float4*)(vp + (long)((s0+si)*2 + b)*EMB + h*64 + d4);
        T[si][d4+0]=u.x; T[si][d4+1]=u.y; T[si][d4+2]=u.z; T[si][d4+3]=u.w;
    }
    __syncthreads();

    #pragma unroll
    for (int j = 0; j < 8; ++j){
        int w = tid + j*256;
        int d = w>>5, sp = w&31;
        unsigned val = packh2(T[2*sp][d], T[2*sp+1][d]);
        vh2[(long)(hb*64 + d)*1024 + (s0>>1) + sp] = val;
    }
}

// ---------------------------------------------------------------------------
// Flash attention: q-tile 128, 4 warps (MI=2), k-tiles 32 double-buffered.
// tf32 QK^T (scores in log2-domain), fp16 PV (C-frags pack to A-frags).
// ---------------------------------------------------------------------------
__global__ __launch_bounds__(128)
void flash_attn(const float* __restrict__ qp, const float* __restrict__ kp,
                const __half* __restrict__ vh, float* __restrict__ op,
                float* __restrict__ gm, float* __restrict__ gl)
{
    __shared__ __align__(16) unsigned SU[9216];
    const int tid = threadIdx.x, lane = tid&31, w = tid>>5;
    const int hb = blockIdx.x, h = hb&15, b = hb>>4;
    const int q0 = blockIdx.y*128;
    const long base = (long)b*EMB + h*DH;
    const float* Qg = qp + base + (long)q0*(BSZ*EMB);
    const float* Kg = kp + base;
    const __half* Vgh = vh + (long)hb*64*2048;

    for (int i = tid; i < 2048; i += 128){
        int r = i>>4, c = (i&15)*4;
        cpa16(&SU[r*72 + c], Qg + (long)r*(BSZ*EMB) + c);
    }
    asm volatile("cp.async.commit_group;\n");
    asm volatile("cp.async.wait_group 0;\n");
    __syncthreads();

    unsigned Qa[8][2][4];
    {
        const int p = lane>>2, col0 = 2*(lane&3);
        #pragma unroll
        for (int ks = 0; ks < 8; ++ks)
            #pragma unroll
            for (int mi = 0; mi < 2; ++mi){
                int m = w*32 + mi*16 + p;
                int col = ks*8 + col0;
                uint2 u0 = *(const uint2*)&SU[ m   *72 + col];
                uint2 u1 = *(const uint2*)&SU[(m+8)*72 + col];
                Qa[ks][mi][0] = u0.x; Qa[ks][mi][1] = u1.x;
                Qa[ks][mi][2] = u0.y; Qa[ks][mi][3] = u1.y;
            }
    }
    __syncthreads();

    unsigned* const Kb0 = SU;
    unsigned* const Kb1 = SU + 2304;
    unsigned* const Vh0 = SU + 4608;
    unsigned* const Vh1 = SU + 5888;

    auto load_kv = [&](int kt, int sel){
        unsigned* Kb = sel ? Kb1 : Kb0;
        unsigned* Vb = sel ? Vh1 : Vh0;
        const long r0 = (long)kt*32;
        #pragma unroll
        for (int j = 0; j < 4; ++j){
            int cch = tid + j*128;
            int r = cch>>4, cc = (cch&15)*4;
            cpa16(&Kb[r*72 + cc], Kg + (r0+r)*(BSZ*EMB) + cc);
        }
        #pragma unroll
        for (int j = 0; j < 2; ++j){
            int u = tid + j*128;
            int d = u>>2, qc = u&3;
            cpa16(&Vb[d*20 + qc*4], Vgh + (long)d*2048 + kt*32 + qc*8);
        }
    };

    float m_[2][2] = {{-1e30f,-1e30f},{-1e30f,-1e30f}};
    float l_[2][2] = {};
    float o[2][8][4] = {};

    load_kv(0, 0);
    asm volatile("cp.async.commit_group;\n");

    for (int t = 0; t < 64; ++t){
        if (t < 63){
            load_kv(t+1, (t+1)&1);
            asm volatile("cp.async.commit_group;\n");
            asm volatile("cp.async.wait_group 1;\n");
        } else {
            asm volatile("cp.async.wait_group 0;\n");
        }
        __syncthreads();

        unsigned* Kb = (t&1) ? Kb1 : Kb0;
        unsigned* Vb = (t&1) ? Vh1 : Vh0;

        float c_[2][4][4] = {};
        #pragma unroll
        for (int ks = 0; ks < 8; ++ks){
            unsigned bf[4][2];
            #pragma unroll
            for (int ni = 0; ni < 4; ++ni){
                int n = ni*8 + (lane>>2);
                int col = ks*8 + 2*(lane&3);
                uint2 u = *(const uint2*)&Kb[n*72 + col];
                bf[ni][0] = u.x; bf[ni][1] = u.y;
            }
            #pragma unroll
            for (int mi = 0; mi < 2; ++mi)
                #pragma unroll
                for (int ni = 0; ni < 4; ++ni)
                    mma8(c_[mi][ni], Qa[ks][mi], bf[ni]);
        }

        // online softmax (log2-domain scores) with rescale-skip
        #pragma unroll
        for (int mi = 0; mi < 2; ++mi){
            float mx0 = -1e30f, mx1 = -1e30f;
            #pragma unroll
            for (int ni = 0; ni < 4; ++ni){
                mx0 = fmaxf(mx0, fmaxf(c_[mi][ni][0], c_[mi][ni][1]));
                mx1 = fmaxf(mx1, fmaxf(c_[mi][ni][2], c_[mi][ni][3]));
            }
            mx0 = fmaxf(mx0, __shfl_xor_sync(0xffffffffu, mx0, 1));
            mx0 = fmaxf(mx0, __shfl_xor_sync(0xffffffffu, mx0, 2));
            mx1 = fmaxf(mx1, __shfl_xor_sync(0xffffffffu, mx1, 1));
            mx1 = fmaxf(mx1, __shfl_xor_sync(0xffffffffu, mx1, 2));
            float mn0 = fmaxf(m_[mi][0], mx0), mn1 = fmaxf(m_[mi][1], mx1);
            if (!__all_sync(0xffffffffu, (mn0 == m_[mi][0]) & (mn1 == m_[mi][1]))){
                float f0 = exp2f(m_[mi][0] - mn0), f1 = exp2f(m_[mi][1] - mn1);
                l_[mi][0] *= f0; l_[mi][1] *= f1;
                #pragma unroll
                for (int ni = 0; ni < 8; ++ni){
                    o[mi][ni][0]*=f0; o[mi][ni][1]*=f0;
                    o[mi][ni][2]*=f1; o[mi][ni][3]*=f1;
                }
                m_[mi][0] = mn0; m_[mi][1] = mn1;
            }
            float s0 = 0.f, s1 = 0.f;
            #pragma unroll
            for (int ni = 0; ni < 4; ++ni){
                c_[mi][ni][0] = exp2f(c_[mi][ni][0]-m_[mi][0]);
                c_[mi][ni][1] = exp2f(c_[mi][ni][1]-m_[mi][0]);
                c_[mi][ni][2] = exp2f(c_[mi][ni][2]-m_[mi][1]);
                c_[mi][ni][3] = exp2f(c_[mi][ni][3]-m_[mi][1]);
                s0 += c_[mi][ni][0]+c_[mi][ni][1];
                s1 += c_[mi][ni][2]+c_[mi][ni][3];
            }
            s0 += __shfl_xor_sync(0xffffffffu, s0, 1);
            s0 += __shfl_xor_sync(0xffffffffu, s0, 2);
            s1 += __shfl_xor_sync(0xffffffffu, s1, 1);
            s1 += __shfl_xor_sync(0xffffffffu, s1, 2);
            l_[mi][0] += s0; l_[mi][1] += s1;
        }

        // P @ V fp16 (no shuffles)
        #pragma unroll
        for (int j = 0; j < 2; ++j){
            unsigned a[2][4];
            #pragma unroll
            for (int mi = 0; mi < 2; ++mi){
                a[mi][0] = packh2(c_[mi][2*j  ][0], c_[mi][2*j  ][1]);
                a[mi][1] = packh2(c_[mi][2*j  ][2], c_[mi][2*j  ][3]);
                a[mi][2] = packh2(c_[mi][2*j+1][0], c_[mi][2*j+1][1]);
                a[mi][3] = packh2(c_[mi][2*j+1][2], c_[mi][2*j+1][3]);
            }
            #pragma unroll
            for (int ni = 0; ni < 8; ++ni){
                int n = ni*8 + (lane>>2);
                unsigned b0 = Vb[n*20 + 8*j + (lane&3)];
                unsigned b1 = Vb[n*20 + 8*j + (lane&3) + 4];
                mma16f16(o[0][ni], a[0], b0, b1);
                mma16f16(o[1][ni], a[1], b0, b1);
            }
        }
        __syncthreads();
    }

    float* Og = op + base + (long)q0*(BSZ*EMB);
    #pragma unroll
    for (int mi = 0; mi < 2; ++mi){
        float inv0 = 1.f/l_[mi][0], inv1 = 1.f/l_[mi][1];
        int m = w*32 + mi*16 + (lane>>2);
        #pragma unroll
        for (int ni = 0; ni < 8; ++ni){
            int d = ni*8 + 2*(lane&3);
            *(float2*)(Og + (long)m    *(BSZ*EMB) + d) = make_float2(o[mi][ni][0]*inv0, o[mi][ni][1]*inv0);
            *(float2*)(Og + (long)(m+8)*(BSZ*EMB) + d) = make_float2(o[mi][ni][2]*inv1, o[mi][ni][3]*inv1);
        }
        if ((lane & 3) == 0){
            gm[(long)hb*S_LEN + q0 + m]     = m_[mi][0];
            gm[(long)hb*S_LEN + q0 + m + 8] = m_[mi][1];
            gl[(long)hb*S_LEN + q0 + m]     = l_[mi][0];
            gl[(long)hb*S_LEN + q0 + m + 8] = l_[mi][1];
        }
    }
}

// ---------------------------------------------------------------------------
// attn_avg: 256 thr, q-tile 128, k-tile 64, warps 4x2 (MI=2, NI=4 — B-frag
// reuse), double-buffered heads, log2-domain exp: acc += exp2(c - e),
// e = m + log2(l) + 4.
// ---------------------------------------------------------------------------
__global__ __launch_bounds__(256)
void avg_attn(const float* __restrict__ qp, const float* __restrict__ kp,
              const float* __restrict__ gm, const float* __restrict__ gl,
              float* __restrict__ avg)
{
    extern __shared__ __align__(16) unsigned ASH[];
    constexpr int BUF = 128*72 + 64*72;
    const int tid = threadIdx.x, lane = tid&31, wid = tid>>5;
    const int wq = wid>>1, wk = wid&1;
    const int k0 = blockIdx.x*64, q0 = blockIdx.y*128, b = blockIdx.z;
    const int p = lane>>2;

    auto stage = [&](int h, int sel){
        unsigned* Qs = ASH + sel*BUF;
        unsigned* Ks = Qs + 128*72;
        const long base = (long)b*EMB + h*DH;
        #pragma unroll
        for (int j = 0; j < 8; ++j){
            int idx = tid + j*256;
            int r = idx>>4, c = (idx&15)*4;
            cpa16(&Qs[r*72 + c], qp + base + (long)(q0+r)*(BSZ*EMB) + c);
        }
        #pragma unroll
        for (int j = 0; j < 4; ++j){
            int idx = tid + j*256;
            int r = idx>>4, c = (idx&15)*4;
            cpa16(&Ks[r*72 + c], kp + base + (long)(k0+r)*(BSZ*EMB) + c);
        }
        asm volatile("cp.async.commit_group;\n");
    };

    float acc[2][4][4] = {};

    stage(0, 0);
    for (int h = 0; h < NH; ++h){
        if (h < NH-1){
            stage(h+1, (h+1)&1);
            asm volatile("cp.async.wait_group 1;\n");
        } else {
            asm volatile("cp.async.wait_group 0;\n");
        }
        __syncthreads();

        unsigned* Qs = ASH + (h&1)*BUF;
        unsigned* Ks = Qs + 128*72;

        float c_[2][4][4] = {};
        #pragma unroll
        for (int ks = 0; ks < 8; ++ks){
            int col = ks*8 + 2*(lane&3);
            unsigned a[2][4];
            #pragma unroll
            for (int mi = 0; mi < 2; ++mi){
                int m = wq*32 + mi*16 + p;
                uint2 u0 = *(const uint2*)&Qs[ m   *72 + col];
                uint2 u1 = *(const uint2*)&Qs[(m+8)*72 + col];
                a[mi][0] = u0.x; a[mi][1] = u1.x; a[mi][2] = u0.y; a[mi][3] = u1.y;
            }
            #pragma unroll
            for (int ni = 0; ni < 4; ++ni){
                int n = wk*32 + ni*8 + p;
                uint2 ub = *(const uint2*)&Ks[n*72 + col];
                unsigned bf[2] = { ub.x, ub.y };
                mma8(c_[0][ni], a[0], bf);
                mma8(c_[1][ni], a[1], bf);
            }
        }

        const int hb = b*NH + h;
        #pragma unroll
        for (int mi = 0; mi < 2; ++mi){
            int r0 = q0 + wq*32 + mi*16 + p;
            float e0 = gm[(long)hb*S_LEN + r0    ] + __log2f(gl[(long)hb*S_LEN + r0    ]) + 4.0f;
            float e1 = gm[(long)hb*S_LEN + r0 + 8] + __log2f(gl[(long)hb*S_LEN + r0 + 8]) + 4.0f;
            #pragma unroll
            for (int ni = 0; ni < 4; ++ni){
                acc[mi][ni][0] += exp2f(c_[mi][ni][0] - e0);
                acc[mi][ni][1] += exp2f(c_[mi][ni][1] - e0);
                acc[mi][ni][2] += exp2f(c_[mi][ni][2] - e1);
                acc[mi][ni][3] += exp2f(c_[mi][ni][3] - e1);
            }
        }
        __syncthreads();
    }

    float* out = avg + (long)b*S2;
    #pragma unroll
    for (int mi = 0; mi < 2; ++mi){
        int r0 = q0 + wq*32 + mi*16 + p;
        #pragma unroll
        for (int ni = 0; ni < 4; ++ni){
            int kc = k0 + wk*32 + ni*8 + 2*(lane&3);
            *(float2*)(out + (long)r0    *S_LEN + kc) = make_float2(acc[mi][ni][0], acc[mi][ni][1]);
            *(float2*)(out + (long)(r0+8)*S_LEN + kc) = make_float2(acc[mi][ni][2], acc[mi][ni][3]);
        }
    }
}

// ---------------------------------------------------------------------------
extern "C" void kernel_launch(void* const* d_in, const int* in_sizes, int n_in,
                              void* d_out, int out_size)
{
    const float* query = (const float*)d_in[0];
    const float* key   = (const float*)d_in[1];
    const float* value = (const float*)d_in[2];
    const float* q_w = (const float*)d_in[3];
    const float* q_b = (const float*)d_in[4];
    const float* k_w = (const float*)d_in[5];
    const float* k_b = (const float*)d_in[6];
    const float* v_w = (const float*)d_in[7];
    const float* v_b = (const float*)d_in[8];
    const float* out_w = (const float*)d_in[9];
    const float* out_b = (const float*)d_in[10];

    float *qp, *kp, *vp, *op, *gm, *gl;
    __half* vh;
    cudaGetSymbolAddress((void**)&qp, g_Qp);
    cudaGetSymbolAddress((void**)&kp, g_Kp);
    cudaGetSymbolAddress((void**)&vp, g_Vp);
    cudaGetSymbolAddress((void**)&vh, g_Vh);
    cudaGetSymbolAddress((void**)&op, g_O);
    cudaGetSymbolAddress((void**)&gm, g_m);
    cudaGetSymbolAddress((void**)&gl, g_l);

    float* Z = (float*)d_out;
    float* attn_avg = (float*)d_out + (long)MROWS*EMB;

    static cudaStream_t s2 = nullptr;
    static cudaEvent_t evFork = nullptr, evJoin = nullptr;
    if (!s2){
        cudaStreamCreateWithFlags(&s2, cudaStreamNonBlocking);
        cudaEventCreateWithFlags(&evFork, cudaEventDisableTiming);
        cudaEventCreateWithFlags(&evJoin, cudaEventDisableTiming);
        cudaFuncSetAttribute(avg_attn, cudaFuncAttributeMaxDynamicSharedMemorySize, 110592);
    }

    // 1) Q/K/V projections (Q pre-scaled into log2 domain)
    dim3 gqkv(EMB/128, MROWS/64, 3);
    qkv_proj<<<gqkv, 256>>>(query, key, value, q_w, q_b, k_w, k_b, v_w, v_b, qp, kp, vp);

    // 1b) V -> fp16 transposed
    dim3 gvt(S_LEN/64, NHEADS, 1);
    v_transpose<<<gvt, 256>>>(vp, (unsigned*)vh);

    // 2) Flash attention
    dim3 gfa(NHEADS, S_LEN/128, 1);
    flash_attn<<<gfa, 128>>>(qp, kp, vh, op, gm, gl);

    // fork: out_proj concurrent with avg_attn
    cudaEventRecord(evFork, 0);
    cudaStreamWaitEvent(s2, evFork, 0);

    dim3 gop(EMB/128, MROWS/64, 1);
    out_proj<<<gop, 256, 0, s2>>>(op, out_w, out_b, Z);
    cudaEventRecord(evJoin, s2);

    dim3 gav(S_LEN/64, S_LEN/128, BSZ);
    avg_attn<<<gav, 256, 110592>>>(qp, kp, gm, gl, attn_avg);

    cudaStreamWaitEvent(0, evJoin, 0);
}

// round 13
// speedup vs baseline: 1.0191x; 1.0191x over previous
#include <cuda_runtime.h>
#include <cuda_fp16.h>

#define S_LEN 2048
#define BSZ   2
#define EMB   1024
#define NH    16
#define DH    64
#define MROWS 4096
#define NHEADS 32
#define S2 ((long)S_LEN*S_LEN)
#define LOG2E 1.4426950408889634f

// Scratch (__device__ globals per alloc-free rule)
__device__ float g_Qp[MROWS*EMB];   // column-pair-permuted, RNA tf32 bits (pre-scaled by 0.125*log2e)
__device__ float g_Kp[MROWS*EMB];   // column-pair-permuted, RNA tf32 bits
__device__ float g_Vp[MROWS*EMB];   // normal layout, fp32
__device__ __half g_Vh[(size_t)MROWS*EMB];  // transposed fp16: row (hb*64+d), col s
__device__ float g_O [MROWS*EMB];
__device__ float g_m [NHEADS*S_LEN];   // log2-domain running max
__device__ float g_l [NHEADS*S_LEN];   // linear sum of exp2(s - m)

__device__ __forceinline__ unsigned f2tf(float f){
    unsigned u; asm("cvt.rna.tf32.f32 %0, %1;" : "=r"(u) : "f"(f)); return u;
}
__device__ __forceinline__ unsigned packh2(float lo, float hi){
    __half2 h = __floats2half2_rn(lo, hi);
    return *(unsigned*)&h;
}
__device__ __forceinline__ void mma8(float* c, const unsigned* a, const unsigned* b){
    asm volatile("mma.sync.aligned.m16n8k8.row.col.f32.tf32.tf32.f32 "
      "{%0,%1,%2,%3}, {%4,%5,%6,%7}, {%8,%9}, {%0,%1,%2,%3};\n"
      : "+f"(c[0]), "+f"(c[1]), "+f"(c[2]), "+f"(c[3])
      : "r"(a[0]), "r"(a[1]), "r"(a[2]), "r"(a[3]), "r"(b[0]), "r"(b[1]));
}
__device__ __forceinline__ void mma16f16(float* c, const unsigned* a, unsigned b0, unsigned b1){
    asm volatile("mma.sync.aligned.m16n8k16.row.col.f32.f16.f16.f32 "
      "{%0,%1,%2,%3}, {%4,%5,%6,%7}, {%8,%9}, {%0,%1,%2,%3};\n"
      : "+f"(c[0]), "+f"(c[1]), "+f"(c[2]), "+f"(c[3])
      : "r"(a[0]), "r"(a[1]), "r"(a[2]), "r"(a[3]), "r"(b0), "r"(b1));
}
__device__ __forceinline__ void cpa16(void* dst, const void* src){
    unsigned d = (unsigned)__cvta_generic_to_shared(dst);
    asm volatile("cp.async.cg.shared.global [%0], [%1], 16;\n" :: "r"(d), "l"(src));
}

// ---------------------------------------------------------------------------
// TN tf32 GEMM body v3: BK=32, pair-group staging -> smem stored column-pair-
// permuted, fragment loads are LDS.64 at stride 40 (conflict-free; verified
// 8p+2q distinct per 16-lane phase). STS conflicts removed by alternating
// store order on odd rows. BM=64, BN=128, WM=32, WN=32, 8 warps.
// Dynamic smem: (2*64 + 2*128)*40*4 = 61440 B.
// permOut: C written column-pair-permuted as RNA tf32 bits.
// ---------------------------------------------------------------------------
__device__ __forceinline__
void gemm_body(const float* __restrict__ A, int lda,
               const float* __restrict__ B, int ldb,
               float* __restrict__ C, int ldc,
               const float* __restrict__ bias, float scale, int K,
               int m0, int n0, bool permOut, unsigned* SM)
{
    constexpr int ST = 40;
    unsigned* const As = SM;            // [2][64][40]
    unsigned* const Bs = SM + 2*64*ST;  // [2][128][40]

    const int tid  = threadIdx.x;
    const int lane = tid & 31, wid = tid >> 5;
    const int wm = wid >> 2, wn = wid & 3;

    const int rA = tid >> 2, gA = (tid & 3) * 8;   // A: one 8-group per thread
    // B: two 8-groups per thread, rows rA and rA+64, same gA

    float acc[2][4][4] = {};
    float4 ra0, ra1, rb[2][2];

    auto ldtiles = [&](int k0){
        ra0 = *(const float4*)(A + (long)(m0+rA)*lda + k0 + gA);
        ra1 = *(const float4*)(A + (long)(m0+rA)*lda + k0 + gA + 4);
        #pragma unroll
        for (int i = 0; i < 2; ++i){
            rb[i][0] = *(const float4*)(B + (long)(n0+rA+i*64)*ldb + k0 + gA);
            rb[i][1] = *(const float4*)(B + (long)(n0+rA+i*64)*ldb + k0 + gA + 4);
        }
    };
    auto sttiles = [&](int buf){
        const int sw = rA & 1;             // odd rows store halves in swapped order
        {
            uint4 u0 = { f2tf(ra0.x), f2tf(ra1.x), f2tf(ra0.y), f2tf(ra1.y) };
            uint4 u1 = { f2tf(ra0.z), f2tf(ra1.z), f2tf(ra0.w), f2tf(ra1.w) };
            unsigned* p = &As[buf*64*ST + rA*ST + gA];
            *(uint4*)(p + (sw?4:0)) = sw ? u1 : u0;
            *(uint4*)(p + (sw?0:4)) = sw ? u0 : u1;
        }
        #pragma unroll
        for (int i = 0; i < 2; ++i){
            uint4 u0 = { f2tf(rb[i][0].x), f2tf(rb[i][1].x), f2tf(rb[i][0].y), f2tf(rb[i][1].y) };
            uint4 u1 = { f2tf(rb[i][0].z), f2tf(rb[i][1].z), f2tf(rb[i][0].w), f2tf(rb[i][1].w) };
            unsigned* p = &Bs[buf*128*ST + (rA+i*64)*ST + gA];
            *(uint4*)(p + (sw?4:0)) = sw ? u1 : u0;
            *(uint4*)(p + (sw?0:4)) = sw ? u0 : u1;
        }
    };
    auto compute = [&](int buf){
        const int p = lane >> 2;
        #pragma unroll
        for (int ks = 0; ks < 4; ++ks){
            const int col = ks*8 + 2*(lane&3);
            unsigned af[2][4], bf[4][2];
            #pragma unroll
            for (int mi = 0; mi < 2; ++mi){
                int m = wm*32 + mi*16 + p;
                uint2 u0 = *(const uint2*)&As[buf*64*ST +  m   *ST + col];
                uint2 u1 = *(const uint2*)&As[buf*64*ST + (m+8)*ST + col];
                af[mi][0] = u0.x; af[mi][1] = u1.x; af[mi][2] = u0.y; af[mi][3] = u1.y;
            }
            #pragma unroll
            for (int ni = 0; ni < 4; ++ni){
                int n = wn*32 + ni*8 + p;
                uint2 ub = *(const uint2*)&Bs[buf*128*ST + n*ST + col];
                bf[ni][0] = ub.x; bf[ni][1] = ub.y;
            }
            #pragma unroll
            for (int mi = 0; mi < 2; ++mi)
                #pragma unroll
                for (int ni = 0; ni < 4; ++ni)
                    mma8(acc[mi][ni], af[mi], bf[ni]);
        }
    };

    ldtiles(0); sttiles(0); __syncthreads();
    const int nk = K/32;
    for (int t = 1; t < nk; ++t){
        ldtiles(t*32);
        compute((t-1)&1);
        sttiles(t&1);
        __syncthreads();
    }
    compute((nk-1)&1);

    #pragma unroll
    for (int mi = 0; mi < 2; ++mi){
        #pragma unroll
        for (int ni = 0; ni < 4; ++ni){
            int m = m0 + wm*32 + mi*16 + (lane>>2);
            int n = n0 + wn*32 + ni*8 + 2*(lane&3);
            float v0 = acc[mi][ni][0], v1 = acc[mi][ni][1];
            float v2 = acc[mi][ni][2], v3 = acc[mi][ni][3];
            float b0 = bias[n], b1 = bias[n+1];
            v0 = (v0+b0)*scale; v1 = (v1+b1)*scale;
            v2 = (v2+b0)*scale; v3 = (v3+b1)*scale;
            if (permOut){
                int p0 = (n & ~7) | ((n&3)<<1) | ((n>>2)&1);
                C[(long)m    *ldc + p0    ] = __uint_as_float(f2tf(v0));
                C[(long)m    *ldc + p0 + 2] = __uint_as_float(f2tf(v1));
                C[(long)(m+8)*ldc + p0    ] = __uint_as_float(f2tf(v2));
                C[(long)(m+8)*ldc + p0 + 2] = __uint_as_float(f2tf(v3));
            } else {
                *(float2*)(C + (long)m    *ldc + n) = make_float2(v0, v1);
                *(float2*)(C + (long)(m+8)*ldc + n) = make_float2(v2, v3);
            }
        }
    }
}

// Merged Q/K/V projections. Q scaled by 0.125*log2e (log2-domain scores).
__global__ __launch_bounds__(256)
void qkv_proj(const float* __restrict__ q, const float* __restrict__ k, const float* __restrict__ v,
              const float* __restrict__ qw, const float* __restrict__ qb,
              const float* __restrict__ kw, const float* __restrict__ kb,
              const float* __restrict__ vw, const float* __restrict__ vb,
              float* __restrict__ qp, float* __restrict__ kp, float* __restrict__ vp)
{
    extern __shared__ __align__(16) unsigned GSM[];
    const int z = blockIdx.z;
    const float* A  = (z==0)? q  : (z==1)? k  : v;
    const float* W  = (z==0)? qw : (z==1)? kw : vw;
    const float* bi = (z==0)? qb : (z==1)? kb : vb;
    float*       C  = (z==0)? qp : (z==1)? kp : vp;
    const float scale = (z==0)? 0.125f*LOG2E : 1.0f;
    gemm_body(A, EMB, W, EMB, C, EMB, bi, scale, EMB,
              blockIdx.y*64, blockIdx.x*128, z<2, GSM);
}

__global__ __launch_bounds__(256)
void out_proj(const float* __restrict__ A, const float* __restrict__ W,
              const float* __restrict__ bi, float* __restrict__ C)
{
    extern __shared__ __align__(16) unsigned GSM[];
    gemm_body(A, EMB, W, EMB, C, EMB, bi, 1.0f, EMB,
              blockIdx.y*64, blockIdx.x*128, false, GSM);
}

// ---------------------------------------------------------------------------
// V transpose+convert: vp fp32 -> vh half [hb*64+d][s].
// ---------------------------------------------------------------------------
__global__ __launch_bounds__(256)
void v_transpose(const float* __restrict__ vp, unsigned* __restrict__ vh2)
{
    __shared__ float T[64][65];
    const int tid = threadIdx.x;
    const int hb = blockIdx.y, h = hb&15, b = hb>>4;
    const int s0 = blockIdx.x*64;

    #pragma unroll
    for (int i = 0; i < 4; ++i){
        int idx = tid + i*256;
        int si = idx>>4, d4 = (idx&15)*4;
        float4 u = *(const float4*)(vp + (long)((s0+si)*2 + b)*EMB + h*64 + d4);
        T[si][d4+0]=u.x; T[si][d4+1]=u.y; T[si][d4+2]=u.z; T[si][d4+3]=u.w;
    }
    __syncthreads();

    #pragma unroll
    for (int j = 0; j < 8; ++j){
        int w = tid + j*256;
        int d = w>>5, sp = w&31;
        unsigned val = packh2(T[2*sp][d], T[2*sp+1][d]);
        vh2[(long)(hb*64 + d)*1024 + (s0>>1) + sp] = val;
    }
}

// ---------------------------------------------------------------------------
// Flash attention: q-tile 128, 4 warps (MI=2), k-tiles 32 double-buffered.
// tf32 QK^T (scores in log2-domain), fp16 PV (C-frags pack to A-frags).
// ---------------------------------------------------------------------------
__global__ __launch_bounds__(128)
void flash_attn(const float* __restrict__ qp, const float* __restrict__ kp,
                const __half* __restrict__ vh, float* __restrict__ op,
                float* __restrict__ gm, float* __restrict__ gl)
{
    __shared__ __align__(16) unsigned SU[9216];
    const int tid = threadIdx.x, lane = tid&31, w = tid>>5;
    const int hb = blockIdx.x, h = hb&15, b = hb>>4;
    const int q0 = blockIdx.y*128;
    const long base = (long)b*EMB + h*DH;
    const float* Qg = qp + base + (long)q0*(BSZ*EMB);
    const float* Kg = kp + base;
    const __half* Vgh = vh + (long)hb*64*2048;

    for (int i = tid; i < 2048; i += 128){
        int r = i>>4, c = (i&15)*4;
        cpa16(&SU[r*72 + c], Qg + (long)r*(BSZ*EMB) + c);
    }
    asm volatile("cp.async.commit_group;\n");
    asm volatile("cp.async.wait_group 0;\n");
    __syncthreads();

    unsigned Qa[8][2][4];
    {
        const int p = lane>>2, col0 = 2*(lane&3);
        #pragma unroll
        for (int ks = 0; ks < 8; ++ks)
            #pragma unroll
            for (int mi = 0; mi < 2; ++mi){
                int m = w*32 + mi*16 + p;
                int col = ks*8 + col0;
                uint2 u0 = *(const uint2*)&SU[ m   *72 + col];
                uint2 u1 = *(const uint2*)&SU[(m+8)*72 + col];
                Qa[ks][mi][0] = u0.x; Qa[ks][mi][1] = u1.x;
                Qa[ks][mi][2] = u0.y; Qa[ks][mi][3] = u1.y;
            }
    }
    __syncthreads();

    unsigned* const Kb0 = SU;
    unsigned* const Kb1 = SU + 2304;
    unsigned* const Vh0 = SU + 4608;
    unsigned* const Vh1 = SU + 5888;

    auto load_kv = [&](int kt, int sel){
        unsigned* Kb = sel ? Kb1 : Kb0;
        unsigned* Vb = sel ? Vh1 : Vh0;
        const long r0 = (long)kt*32;
        #pragma unroll
        for (int j = 0; j < 4; ++j){
            int cch = tid + j*128;
            int r = cch>>4, cc = (cch&15)*4;
            cpa16(&Kb[r*72 + cc], Kg + (r0+r)*(BSZ*EMB) + cc);
        }
        #pragma unroll
        for (int j = 0; j < 2; ++j){
            int u = tid + j*128;
            int d = u>>2, qc = u&3;
            cpa16(&Vb[d*20 + qc*4], Vgh + (long)d*2048 + kt*32 + qc*8);
        }
    };

    float m_[2][2] = {{-1e30f,-1e30f},{-1e30f,-1e30f}};
    float l_[2][2] = {};
    float o[2][8][4] = {};

    load_kv(0, 0);
    asm volatile("cp.async.commit_group;\n");

    for (int t = 0; t < 64; ++t){
        if (t < 63){
            load_kv(t+1, (t+1)&1);
            asm volatile("cp.async.commit_group;\n");
            asm volatile("cp.async.wait_group 1;\n");
        } else {
            asm volatile("cp.async.wait_group 0;\n");
        }
        __syncthreads();

        unsigned* Kb = (t&1) ? Kb1 : Kb0;
        unsigned* Vb = (t&1) ? Vh1 : Vh0;

        float c_[2][4][4] = {};
        #pragma unroll
        for (int ks = 0; ks < 8; ++ks){
            unsigned bf[4][2];
            #pragma unroll
            for (int ni = 0; ni < 4; ++ni){
                int n = ni*8 + (lane>>2);
                int col = ks*8 + 2*(lane&3);
                uint2 u = *(const uint2*)&Kb[n*72 + col];
                bf[ni][0] = u.x; bf[ni][1] = u.y;
            }
            #pragma unroll
            for (int mi = 0; mi < 2; ++mi)
                #pragma unroll
                for (int ni = 0; ni < 4; ++ni)
                    mma8(c_[mi][ni], Qa[ks][mi], bf[ni]);
        }

        // online softmax (log2-domain) with rescale-skip
        #pragma unroll
        for (int mi = 0; mi < 2; ++mi){
            float mx0 = -1e30f, mx1 = -1e30f;
            #pragma unroll
            for (int ni = 0; ni < 4; ++ni){
                mx0 = fmaxf(mx0, fmaxf(c_[mi][ni][0], c_[mi][ni][1]));
                mx1 = fmaxf(mx1, fmaxf(c_[mi][ni][2], c_[mi][ni][3]));
            }
            mx0 = fmaxf(mx0, __shfl_xor_sync(0xffffffffu, mx0, 1));
            mx0 = fmaxf(mx0, __shfl_xor_sync(0xffffffffu, mx0, 2));
            mx1 = fmaxf(mx1, __shfl_xor_sync(0xffffffffu, mx1, 1));
            mx1 = fmaxf(mx1, __shfl_xor_sync(0xffffffffu, mx1, 2));
            float mn0 = fmaxf(m_[mi][0], mx0), mn1 = fmaxf(m_[mi][1], mx1);
            if (!__all_sync(0xffffffffu, (mn0 == m_[mi][0]) & (mn1 == m_[mi][1]))){
                float f0 = exp2f(m_[mi][0] - mn0), f1 = exp2f(m_[mi][1] - mn1);
                l_[mi][0] *= f0; l_[mi][1] *= f1;
                #pragma unroll
                for (int ni = 0; ni < 8; ++ni){
                    o[mi][ni][0]*=f0; o[mi][ni][1]*=f0;
                    o[mi][ni][2]*=f1; o[mi][ni][3]*=f1;
                }
                m_[mi][0] = mn0; m_[mi][1] = mn1;
            }
            float s0 = 0.f, s1 = 0.f;
            #pragma unroll
            for (int ni = 0; ni < 4; ++ni){
                c_[mi][ni][0] = exp2f(c_[mi][ni][0]-m_[mi][0]);
                c_[mi][ni][1] = exp2f(c_[mi][ni][1]-m_[mi][0]);
                c_[mi][ni][2] = exp2f(c_[mi][ni][2]-m_[mi][1]);
                c_[mi][ni][3] = exp2f(c_[mi][ni][3]-m_[mi][1]);
                s0 += c_[mi][ni][0]+c_[mi][ni][1];
                s1 += c_[mi][ni][2]+c_[mi][ni][3];
            }
            s0 += __shfl_xor_sync(0xffffffffu, s0, 1);
            s0 += __shfl_xor_sync(0xffffffffu, s0, 2);
            s1 += __shfl_xor_sync(0xffffffffu, s1, 1);
            s1 += __shfl_xor_sync(0xffffffffu, s1, 2);
            l_[mi][0] += s0; l_[mi][1] += s1;
        }

        // P @ V fp16 (no shuffles)
        #pragma unroll
        for (int j = 0; j < 2; ++j){
            unsigned a[2][4];
            #pragma unroll
            for (int mi = 0; mi < 2; ++mi){
                a[mi][0] = packh2(c_[mi][2*j  ][0], c_[mi][2*j  ][1]);
                a[mi][1] = packh2(c_[mi][2*j  ][2], c_[mi][2*j  ][3]);
                a[mi][2] = packh2(c_[mi][2*j+1][0], c_[mi][2*j+1][1]);
                a[mi][3] = packh2(c_[mi][2*j+1][2], c_[mi][2*j+1][3]);
            }
            #pragma unroll
            for (int ni = 0; ni < 8; ++ni){
                int n = ni*8 + (lane>>2);
                unsigned b0 = Vb[n*20 + 8*j + (lane&3)];
                unsigned b1 = Vb[n*20 + 8*j + (lane&3) + 4];
                mma16f16(o[0][ni], a[0], b0, b1);
                mma16f16(o[1][ni], a[1], b0, b1);
            }
        }
        __syncthreads();
    }

    float* Og = op + base + (long)q0*(BSZ*EMB);
    #pragma unroll
    for (int mi = 0; mi < 2; ++mi){
        float inv0 = 1.f/l_[mi][0], inv1 = 1.f/l_[mi][1];
        int m = w*32 + mi*16 + (lane>>2);
        #pragma unroll
        for (int ni = 0; ni < 8; ++ni){
            int d = ni*8 + 2*(lane&3);
            *(float2*)(Og + (long)m    *(BSZ*EMB) + d) = make_float2(o[mi][ni][0]*inv0, o[mi][ni][1]*inv0);
            *(float2*)(Og + (long)(m+8)*(BSZ*EMB) + d) = make_float2(o[mi][ni][2]*inv1, o[mi][ni][3]*inv1);
        }
        if ((lane & 3) == 0){
            gm[(long)hb*S_LEN + q0 + m]     = m_[mi][0];
            gm[(long)hb*S_LEN + q0 + m + 8] = m_[mi][1];
            gl[(long)hb*S_LEN + q0 + m]     = l_[mi][0];
            gl[(long)hb*S_LEN + q0 + m + 8] = l_[mi][1];
        }
    }
}

// ---------------------------------------------------------------------------
// attn_avg: 256 thr, q-tile 128, k-tile 64, warps 4x2 (MI=2, NI=4),
// double-buffered heads, log2-domain exp2.
// ---------------------------------------------------------------------------
__global__ __launch_bounds__(256)
void avg_attn(const float* __restrict__ qp, const float* __restrict__ kp,
              const float* __restrict__ gm, const float* __restrict__ gl,
              float* __restrict__ avg)
{
    extern __shared__ __align__(16) unsigned ASH[];
    constexpr int BUF = 128*72 + 64*72;
    const int tid = threadIdx.x, lane = tid&31, wid = tid>>5;
    const int wq = wid>>1, wk = wid&1;
    const int k0 = blockIdx.x*64, q0 = blockIdx.y*128, b = blockIdx.z;
    const int p = lane>>2;

    auto stage = [&](int h, int sel){
        unsigned* Qs = ASH + sel*BUF;
        unsigned* Ks = Qs + 128*72;
        const long base = (long)b*EMB + h*DH;
        #pragma unroll
        for (int j = 0; j < 8; ++j){
            int idx = tid + j*256;
            int r = idx>>4, c = (idx&15)*4;
            cpa16(&Qs[r*72 + c], qp + base + (long)(q0+r)*(BSZ*EMB) + c);
        }
        #pragma unroll
        for (int j = 0; j < 4; ++j){
            int idx = tid + j*256;
            int r = idx>>4, c = (idx&15)*4;
            cpa16(&Ks[r*72 + c], kp + base + (long)(k0+r)*(BSZ*EMB) + c);
        }
        asm volatile("cp.async.commit_group;\n");
    };

    float acc[2][4][4] = {};

    stage(0, 0);
    for (int h = 0; h < NH; ++h){
        if (h < NH-1){
            stage(h+1, (h+1)&1);
            asm volatile("cp.async.wait_group 1;\n");
        } else {
            asm volatile("cp.async.wait_group 0;\n");
        }
        __syncthreads();

        unsigned* Qs = ASH + (h&1)*BUF;
        unsigned* Ks = Qs + 128*72;

        float c_[2][4][4] = {};
        #pragma unroll
        for (int ks = 0; ks < 8; ++ks){
            int col = ks*8 + 2*(lane&3);
            unsigned a[2][4];
            #pragma unroll
            for (int mi = 0; mi < 2; ++mi){
                int m = wq*32 + mi*16 + p;
                uint2 u0 = *(const uint2*)&Qs[ m   *72 + col];
                uint2 u1 = *(const uint2*)&Qs[(m+8)*72 + col];
                a[mi][0] = u0.x; a[mi][1] = u1.x; a[mi][2] = u0.y; a[mi][3] = u1.y;
            }
            #pragma unroll
            for (int ni = 0; ni < 4; ++ni){
                int n = wk*32 + ni*8 + p;
                uint2 ub = *(const uint2*)&Ks[n*72 + col];
                unsigned bf[2] = { ub.x, ub.y };
                mma8(c_[0][ni], a[0], bf);
                mma8(c_[1][ni], a[1], bf);
            }
        }

        const int hb = b*NH + h;
        #pragma unroll
        for (int mi = 0; mi < 2; ++mi){
            int r0 = q0 + wq*32 + mi*16 + p;
            float e0 = gm[(long)hb*S_LEN + r0    ] + __log2f(gl[(long)hb*S_LEN + r0    ]) + 4.0f;
            float e1 = gm[(long)hb*S_LEN + r0 + 8] + __log2f(gl[(long)hb*S_LEN + r0 + 8]) + 4.0f;
            #pragma unroll
            for (int ni = 0; ni < 4; ++ni){
                acc[mi][ni][0] += exp2f(c_[mi][ni][0] - e0);
                acc[mi][ni][1] += exp2f(c_[mi][ni][1] - e0);
                acc[mi][ni][2] += exp2f(c_[mi][ni][2] - e1);
                acc[mi][ni][3] += exp2f(c_[mi][ni][3] - e1);
            }
        }
        __syncthreads();
    }

    float* out = avg + (long)b*S2;
    #pragma unroll
    for (int mi = 0; mi < 2; ++mi){
        int r0 = q0 + wq*32 + mi*16 + p;
        #pragma unroll
        for (int ni = 0; ni < 4; ++ni){
            int kc = k0 + wk*32 + ni*8 + 2*(lane&3);
            *(float2*)(out + (long)r0    *S_LEN + kc) = make_float2(acc[mi][ni][0], acc[mi][ni][1]);
            *(float2*)(out + (long)(r0+8)*S_LEN + kc) = make_float2(acc[mi][ni][2], acc[mi][ni][3]);
        }
    }
}

// ---------------------------------------------------------------------------
extern "C" void kernel_launch(void* const* d_in, const int* in_sizes, int n_in,
                              void* d_out, int out_size)
{
    const float* query = (const float*)d_in[0];
    const float* key   = (const float*)d_in[1];
    const float* value = (const float*)d_in[2];
    const float* q_w = (const float*)d_in[3];
    const float* q_b = (const float*)d_in[4];
    const float* k_w = (const float*)d_in[5];
    const float* k_b = (const float*)d_in[6];
    const float* v_w = (const float*)d_in[7];
    const float* v_b = (const float*)d_in[8];
    const float* out_w = (const float*)d_in[9];
    const float* out_b = (const float*)d_in[10];

    float *qp, *kp, *vp, *op, *gm, *gl;
    __half* vh;
    cudaGetSymbolAddress((void**)&qp, g_Qp);
    cudaGetSymbolAddress((void**)&kp, g_Kp);
    cudaGetSymbolAddress((void**)&vp, g_Vp);
    cudaGetSymbolAddress((void**)&vh, g_Vh);
    cudaGetSymbolAddress((void**)&op, g_O);
    cudaGetSymbolAddress((void**)&gm, g_m);
    cudaGetSymbolAddress((void**)&gl, g_l);

    float* Z = (float*)d_out;
    float* attn_avg = (float*)d_out + (long)MROWS*EMB;

    static cudaStream_t s2 = nullptr;
    static cudaEvent_t evFork = nullptr, evJoin = nullptr;
    if (!s2){
        cudaStreamCreateWithFlags(&s2, cudaStreamNonBlocking);
        cudaEventCreateWithFlags(&evFork, cudaEventDisableTiming);
        cudaEventCreateWithFlags(&evJoin, cudaEventDisableTiming);
        cudaFuncSetAttribute(avg_attn,  cudaFuncAttributeMaxDynamicSharedMemorySize, 110592);
        cudaFuncSetAttribute(qkv_proj,  cudaFuncAttributeMaxDynamicSharedMemorySize, 61440);
        cudaFuncSetAttribute(out_proj,  cudaFuncAttributeMaxDynamicSharedMemorySize, 61440);
    }

    // 1) Q/K/V projections (Q pre-scaled into log2 domain)
    dim3 gqkv(EMB/128, MROWS/64, 3);
    qkv_proj<<<gqkv, 256, 61440>>>(query, key, value, q_w, q_b, k_w, k_b, v_w, v_b, qp, kp, vp);

    // 1b) V -> fp16 transposed
    dim3 gvt(S_LEN/64, NHEADS, 1);
    v_transpose<<<gvt, 256>>>(vp, (unsigned*)vh);

    // 2) Flash attention
    dim3 gfa(NHEADS, S_LEN/128, 1);
    flash_attn<<<gfa, 128>>>(qp, kp, vh, op, gm, gl);

    // fork: out_proj concurrent with avg_attn
    cudaEventRecord(evFork, 0);
    cudaStreamWaitEvent(s2, evFork, 0);

    dim3 gop(EMB/128, MROWS/64, 1);
    out_proj<<<gop, 256, 61440, s2>>>(op, out_w, out_b, Z);
    cudaEventRecord(evJoin, s2);

    dim3 gav(S_LEN/64, S_LEN/128, BSZ);
    avg_attn<<<gav, 256, 110592>>>(qp, kp, gm, gl, attn_avg);

    cudaStreamWaitEvent(0, evJoin, 0);
}

// round 14
// speedup vs baseline: 1.0935x; 1.0730x over previous
#include <cuda_runtime.h>
#include <cuda_fp16.h>

#define S_LEN 2048
#define BSZ   2
#define EMB   1024
#define NH    16
#define DH    64
#define MROWS 4096
#define NHEADS 32
#define S2 ((long)S_LEN*S_LEN)
#define LOG2E 1.4426950408889634f

// Scratch (__device__ globals per alloc-free rule)
__device__ float g_Qp[MROWS*EMB];   // column-pair-permuted, RNA tf32 bits (pre-scaled 0.125*log2e)
__device__ float g_Kp[MROWS*EMB];   // column-pair-permuted, RNA tf32 bits
__device__ float g_Vp[MROWS*EMB];   // normal layout, fp32
__device__ __half g_Vh[(size_t)MROWS*EMB];  // transposed fp16: row (hb*64+d), col s
__device__ float g_O [MROWS*EMB];
__device__ float g_m [NHEADS*S_LEN];   // log2-domain running max
__device__ float g_l [NHEADS*S_LEN];   // linear sum of exp2(s - m)

__device__ __forceinline__ unsigned f2tf(float f){
    unsigned u; asm("cvt.rna.tf32.f32 %0, %1;" : "=r"(u) : "f"(f)); return u;
}
__device__ __forceinline__ unsigned packh2(float lo, float hi){
    __half2 h = __floats2half2_rn(lo, hi);
    return *(unsigned*)&h;
}
__device__ __forceinline__ void mma8(float* c, const unsigned* a, const unsigned* b){
    asm volatile("mma.sync.aligned.m16n8k8.row.col.f32.tf32.tf32.f32 "
      "{%0,%1,%2,%3}, {%4,%5,%6,%7}, {%8,%9}, {%0,%1,%2,%3};\n"
      : "+f"(c[0]), "+f"(c[1]), "+f"(c[2]), "+f"(c[3])
      : "r"(a[0]), "r"(a[1]), "r"(a[2]), "r"(a[3]), "r"(b[0]), "r"(b[1]));
}
__device__ __forceinline__ void mma16f16(float* c, const unsigned* a, unsigned b0, unsigned b1){
    asm volatile("mma.sync.aligned.m16n8k16.row.col.f32.f16.f16.f32 "
      "{%0,%1,%2,%3}, {%4,%5,%6,%7}, {%8,%9}, {%0,%1,%2,%3};\n"
      : "+f"(c[0]), "+f"(c[1]), "+f"(c[2]), "+f"(c[3])
      : "r"(a[0]), "r"(a[1]), "r"(a[2]), "r"(a[3]), "r"(b0), "r"(b1));
}
__device__ __forceinline__ void cpa16(void* dst, const void* src){
    unsigned d = (unsigned)__cvta_generic_to_shared(dst);
    asm volatile("cp.async.cg.shared.global [%0], [%1], 16;\n" :: "r"(d), "l"(src));
}

// ---------------------------------------------------------------------------
// TN tf32 GEMM body v4: BM=128, BN=128, BK=32, WM=64 (MI=4), WN=32 (NI=4),
// 8 warps. Pair-group staging (stride 40, odd-row swap — proven round 13),
// LDS.64 fragments, uniform per-thread mapping (no divergence).
// Dynamic smem: 2*(2*128*40)*4 = 81920 B.
// permOut: C written column-pair-permuted as RNA tf32 bits.
// ---------------------------------------------------------------------------
__device__ __forceinline__
void gemm_body(const float* __restrict__ A, int lda,
               const float* __restrict__ B, int ldb,
               float* __restrict__ C, int ldc,
               const float* __restrict__ bias, float scale, int K,
               int m0, int n0, bool permOut, unsigned* SM)
{
    constexpr int ST = 40;
    unsigned* const As = SM;             // [2][128][40]
    unsigned* const Bs = SM + 2*128*ST;  // [2][128][40]

    const int tid  = threadIdx.x;
    const int lane = tid & 31, wid = tid >> 5;
    const int wm = wid >> 2, wn = wid & 3;

    float acc[4][4][4] = {};
    float4 ra[2][2], rb[2][2];

    auto ldtiles = [&](int k0){
        #pragma unroll
        for (int i = 0; i < 2; ++i){
            int g = tid + i*256;
            int r = g>>2, c8 = (g&3)*8;
            ra[i][0] = *(const float4*)(A + (long)(m0+r)*lda + k0 + c8);
            ra[i][1] = *(const float4*)(A + (long)(m0+r)*lda + k0 + c8 + 4);
            rb[i][0] = *(const float4*)(B + (long)(n0+r)*ldb + k0 + c8);
            rb[i][1] = *(const float4*)(B + (long)(n0+r)*ldb + k0 + c8 + 4);
        }
    };
    auto sttiles = [&](int buf){
        #pragma unroll
        for (int i = 0; i < 2; ++i){
            int g = tid + i*256;
            int r = g>>2, c8 = (g&3)*8;
            const int sw = r & 1;
            uint4 u0 = { f2tf(ra[i][0].x), f2tf(ra[i][1].x), f2tf(ra[i][0].y), f2tf(ra[i][1].y) };
            uint4 u1 = { f2tf(ra[i][0].z), f2tf(ra[i][1].z), f2tf(ra[i][0].w), f2tf(ra[i][1].w) };
            unsigned* p = &As[buf*128*ST + r*ST + c8];
            *(uint4*)(p + (sw?4:0)) = sw ? u1 : u0;
            *(uint4*)(p + (sw?0:4)) = sw ? u0 : u1;
            uint4 v0 = { f2tf(rb[i][0].x), f2tf(rb[i][1].x), f2tf(rb[i][0].y), f2tf(rb[i][1].y) };
            uint4 v1 = { f2tf(rb[i][0].z), f2tf(rb[i][1].z), f2tf(rb[i][0].w), f2tf(rb[i][1].w) };
            unsigned* q = &Bs[buf*128*ST + r*ST + c8];
            *(uint4*)(q + (sw?4:0)) = sw ? v1 : v0;
            *(uint4*)(q + (sw?0:4)) = sw ? v0 : v1;
        }
    };
    auto compute = [&](int buf){
        const int p = lane >> 2;
        #pragma unroll
        for (int ks = 0; ks < 4; ++ks){
            const int col = ks*8 + 2*(lane&3);
            unsigned af[4][4], bf[4][2];
            #pragma unroll
            for (int mi = 0; mi < 4; ++mi){
                int m = wm*64 + mi*16 + p;
                uint2 u0 = *(const uint2*)&As[buf*128*ST +  m   *ST + col];
                uint2 u1 = *(const uint2*)&As[buf*128*ST + (m+8)*ST + col];
                af[mi][0] = u0.x; af[mi][1] = u1.x; af[mi][2] = u0.y; af[mi][3] = u1.y;
            }
            #pragma unroll
            for (int ni = 0; ni < 4; ++ni){
                int n = wn*32 + ni*8 + p;
                uint2 ub = *(const uint2*)&Bs[buf*128*ST + n*ST + col];
                bf[ni][0] = ub.x; bf[ni][1] = ub.y;
            }
            #pragma unroll
            for (int mi = 0; mi < 4; ++mi)
                #pragma unroll
                for (int ni = 0; ni < 4; ++ni)
                    mma8(acc[mi][ni], af[mi], bf[ni]);
        }
    };

    ldtiles(0); sttiles(0); __syncthreads();
    const int nk = K/32;
    for (int t = 1; t < nk; ++t){
        ldtiles(t*32);
        compute((t-1)&1);
        sttiles(t&1);
        __syncthreads();
    }
    compute((nk-1)&1);

    #pragma unroll
    for (int mi = 0; mi < 4; ++mi){
        #pragma unroll
        for (int ni = 0; ni < 4; ++ni){
            int m = m0 + wm*64 + mi*16 + (lane>>2);
            int n = n0 + wn*32 + ni*8 + 2*(lane&3);
            float v0 = acc[mi][ni][0], v1 = acc[mi][ni][1];
            float v2 = acc[mi][ni][2], v3 = acc[mi][ni][3];
            float b0 = bias[n], b1 = bias[n+1];
            v0 = (v0+b0)*scale; v1 = (v1+b1)*scale;
            v2 = (v2+b0)*scale; v3 = (v3+b1)*scale;
            if (permOut){
                int p0 = (n & ~7) | ((n&3)<<1) | ((n>>2)&1);
                C[(long)m    *ldc + p0    ] = __uint_as_float(f2tf(v0));
                C[(long)m    *ldc + p0 + 2] = __uint_as_float(f2tf(v1));
                C[(long)(m+8)*ldc + p0    ] = __uint_as_float(f2tf(v2));
                C[(long)(m+8)*ldc + p0 + 2] = __uint_as_float(f2tf(v3));
            } else {
                *(float2*)(C + (long)m    *ldc + n) = make_float2(v0, v1);
                *(float2*)(C + (long)(m+8)*ldc + n) = make_float2(v2, v3);
            }
        }
    }
}

// Merged Q/K/V projections. Q scaled by 0.125*log2e (log2-domain scores).
__global__ __launch_bounds__(256)
void qkv_proj(const float* __restrict__ q, const float* __restrict__ k, const float* __restrict__ v,
              const float* __restrict__ qw, const float* __restrict__ qb,
              const float* __restrict__ kw, const float* __restrict__ kb,
              const float* __restrict__ vw, const float* __restrict__ vb,
              float* __restrict__ qp, float* __restrict__ kp, float* __restrict__ vp)
{
    extern __shared__ __align__(16) unsigned GSM[];
    const int z = blockIdx.z;
    const float* A  = (z==0)? q  : (z==1)? k  : v;
    const float* W  = (z==0)? qw : (z==1)? kw : vw;
    const float* bi = (z==0)? qb : (z==1)? kb : vb;
    float*       C  = (z==0)? qp : (z==1)? kp : vp;
    const float scale = (z==0)? 0.125f*LOG2E : 1.0f;
    gemm_body(A, EMB, W, EMB, C, EMB, bi, scale, EMB,
              blockIdx.y*128, blockIdx.x*128, z<2, GSM);
}

__global__ __launch_bounds__(256)
void out_proj(const float* __restrict__ A, const float* __restrict__ W,
              const float* __restrict__ bi, float* __restrict__ C)
{
    extern __shared__ __align__(16) unsigned GSM[];
    gemm_body(A, EMB, W, EMB, C, EMB, bi, 1.0f, EMB,
              blockIdx.y*128, blockIdx.x*128, false, GSM);
}

// ---------------------------------------------------------------------------
// V transpose+convert: vp fp32 -> vh half [hb*64+d][s].
// ---------------------------------------------------------------------------
__global__ __launch_bounds__(256)
void v_transpose(const float* __restrict__ vp, unsigned* __restrict__ vh2)
{
    __shared__ float T[64][65];
    const int tid = threadIdx.x;
    const int hb = blockIdx.y, h = hb&15, b = hb>>4;
    const int s0 = blockIdx.x*64;

    #pragma unroll
    for (int i = 0; i < 4; ++i){
        int idx = tid + i*256;
        int si = idx>>4, d4 = (idx&15)*4;
        float4 u = *(const float4*)(vp + (long)((s0+si)*2 + b)*EMB + h*64 + d4);
        T[si][d4+0]=u.x; T[si][d4+1]=u.y; T[si][d4+2]=u.z; T[si][d4+3]=u.w;
    }
    __syncthreads();

    #pragma unroll
    for (int j = 0; j < 8; ++j){
        int w = tid + j*256;
        int d = w>>5, sp = w&31;
        unsigned val = packh2(T[2*sp][d], T[2*sp+1][d]);
        vh2[(long)(hb*64 + d)*1024 + (s0>>1) + sp] = val;
    }
}

// ---------------------------------------------------------------------------
// Flash attention (round-13 exact): q-tile 128, 4 warps (MI=2), k-tiles 32
// double-buffered. tf32 QK^T (log2-domain scores), fp16 PV.
// ---------------------------------------------------------------------------
__global__ __launch_bounds__(128)
void flash_attn(const float* __restrict__ qp, const float* __restrict__ kp,
                const __half* __restrict__ vh, float* __restrict__ op,
                float* __restrict__ gm, float* __restrict__ gl)
{
    __shared__ __align__(16) unsigned SU[9216];
    const int tid = threadIdx.x, lane = tid&31, w = tid>>5;
    const int hb = blockIdx.x, h = hb&15, b = hb>>4;
    const int q0 = blockIdx.y*128;
    const long base = (long)b*EMB + h*DH;
    const float* Qg = qp + base + (long)q0*(BSZ*EMB);
    const float* Kg = kp + base;
    const __half* Vgh = vh + (long)hb*64*2048;

    for (int i = tid; i < 2048; i += 128){
        int r = i>>4, c = (i&15)*4;
        cpa16(&SU[r*72 + c], Qg + (long)r*(BSZ*EMB) + c);
    }
    asm volatile("cp.async.commit_group;\n");
    asm volatile("cp.async.wait_group 0;\n");
    __syncthreads();

    unsigned Qa[8][2][4];
    {
        const int p = lane>>2, col0 = 2*(lane&3);
        #pragma unroll
        for (int ks = 0; ks < 8; ++ks)
            #pragma unroll
            for (int mi = 0; mi < 2; ++mi){
                int m = w*32 + mi*16 + p;
                int col = ks*8 + col0;
                uint2 u0 = *(const uint2*)&SU[ m   *72 + col];
                uint2 u1 = *(const uint2*)&SU[(m+8)*72 + col];
                Qa[ks][mi][0] = u0.x; Qa[ks][mi][1] = u1.x;
                Qa[ks][mi][2] = u0.y; Qa[ks][mi][3] = u1.y;
            }
    }
    __syncthreads();

    unsigned* const Kb0 = SU;
    unsigned* const Kb1 = SU + 2304;
    unsigned* const Vh0 = SU + 4608;
    unsigned* const Vh1 = SU + 5888;

    auto load_kv = [&](int kt, int sel){
        unsigned* Kb = sel ? Kb1 : Kb0;
        unsigned* Vb = sel ? Vh1 : Vh0;
        const long r0 = (long)kt*32;
        #pragma unroll
        for (int j = 0; j < 4; ++j){
            int cch = tid + j*128;
            int r = cch>>4, cc = (cch&15)*4;
            cpa16(&Kb[r*72 + cc], Kg + (r0+r)*(BSZ*EMB) + cc);
        }
        #pragma unroll
        for (int j = 0; j < 2; ++j){
            int u = tid + j*128;
            int d = u>>2, qc = u&3;
            cpa16(&Vb[d*20 + qc*4], Vgh + (long)d*2048 + kt*32 + qc*8);
        }
    };

    float m_[2][2] = {{-1e30f,-1e30f},{-1e30f,-1e30f}};
    float l_[2][2] = {};
    float o[2][8][4] = {};

    load_kv(0, 0);
    asm volatile("cp.async.commit_group;\n");

    for (int t = 0; t < 64; ++t){
        if (t < 63){
            load_kv(t+1, (t+1)&1);
            asm volatile("cp.async.commit_group;\n");
            asm volatile("cp.async.wait_group 1;\n");
        } else {
            asm volatile("cp.async.wait_group 0;\n");
        }
        __syncthreads();

        unsigned* Kb = (t&1) ? Kb1 : Kb0;
        unsigned* Vb = (t&1) ? Vh1 : Vh0;

        float c_[2][4][4] = {};
        #pragma unroll
        for (int ks = 0; ks < 8; ++ks){
            unsigned bf[4][2];
            #pragma unroll
            for (int ni = 0; ni < 4; ++ni){
                int n = ni*8 + (lane>>2);
                int col = ks*8 + 2*(lane&3);
                uint2 u = *(const uint2*)&Kb[n*72 + col];
                bf[ni][0] = u.x; bf[ni][1] = u.y;
            }
            #pragma unroll
            for (int mi = 0; mi < 2; ++mi)
                #pragma unroll
                for (int ni = 0; ni < 4; ++ni)
                    mma8(c_[mi][ni], Qa[ks][mi], bf[ni]);
        }

        // online softmax (log2-domain) with rescale-skip
        #pragma unroll
        for (int mi = 0; mi < 2; ++mi){
            float mx0 = -1e30f, mx1 = -1e30f;
            #pragma unroll
            for (int ni = 0; ni < 4; ++ni){
                mx0 = fmaxf(mx0, fmaxf(c_[mi][ni][0], c_[mi][ni][1]));
                mx1 = fmaxf(mx1, fmaxf(c_[mi][ni][2], c_[mi][ni][3]));
            }
            mx0 = fmaxf(mx0, __shfl_xor_sync(0xffffffffu, mx0, 1));
            mx0 = fmaxf(mx0, __shfl_xor_sync(0xffffffffu, mx0, 2));
            mx1 = fmaxf(mx1, __shfl_xor_sync(0xffffffffu, mx1, 1));
            mx1 = fmaxf(mx1, __shfl_xor_sync(0xffffffffu, mx1, 2));
            float mn0 = fmaxf(m_[mi][0], mx0), mn1 = fmaxf(m_[mi][1], mx1);
            if (!__all_sync(0xffffffffu, (mn0 == m_[mi][0]) & (mn1 == m_[mi][1]))){
                float f0 = exp2f(m_[mi][0] - mn0), f1 = exp2f(m_[mi][1] - mn1);
                l_[mi][0] *= f0; l_[mi][1] *= f1;
                #pragma unroll
                for (int ni = 0; ni < 8; ++ni){
                    o[mi][ni][0]*=f0; o[mi][ni][1]*=f0;
                    o[mi][ni][2]*=f1; o[mi][ni][3]*=f1;
                }
                m_[mi][0] = mn0; m_[mi][1] = mn1;
            }
            float s0 = 0.f, s1 = 0.f;
            #pragma unroll
            for (int ni = 0; ni < 4; ++ni){
                c_[mi][ni][0] = exp2f(c_[mi][ni][0]-m_[mi][0]);
                c_[mi][ni][1] = exp2f(c_[mi][ni][1]-m_[mi][0]);
                c_[mi][ni][2] = exp2f(c_[mi][ni][2]-m_[mi][1]);
                c_[mi][ni][3] = exp2f(c_[mi][ni][3]-m_[mi][1]);
                s0 += c_[mi][ni][0]+c_[mi][ni][1];
                s1 += c_[mi][ni][2]+c_[mi][ni][3];
            }
            s0 += __shfl_xor_sync(0xffffffffu, s0, 1);
            s0 += __shfl_xor_sync(0xffffffffu, s0, 2);
            s1 += __shfl_xor_sync(0xffffffffu, s1, 1);
            s1 += __shfl_xor_sync(0xffffffffu, s1, 2);
            l_[mi][0] += s0; l_[mi][1] += s1;
        }

        // P @ V fp16 (no shuffles)
        #pragma unroll
        for (int j = 0; j < 2; ++j){
            unsigned a[2][4];
            #pragma unroll
            for (int mi = 0; mi < 2; ++mi){
                a[mi][0] = packh2(c_[mi][2*j  ][0], c_[mi][2*j  ][1]);
                a[mi][1] = packh2(c_[mi][2*j  ][2], c_[mi][2*j  ][3]);
                a[mi][2] = packh2(c_[mi][2*j+1][0], c_[mi][2*j+1][1]);
                a[mi][3] = packh2(c_[mi][2*j+1][2], c_[mi][2*j+1][3]);
            }
            #pragma unroll
            for (int ni = 0; ni < 8; ++ni){
                int n = ni*8 + (lane>>2);
                unsigned b0 = Vb[n*20 + 8*j + (lane&3)];
                unsigned b1 = Vb[n*20 + 8*j + (lane&3) + 4];
                mma16f16(o[0][ni], a[0], b0, b1);
                mma16f16(o[1][ni], a[1], b0, b1);
            }
        }
        __syncthreads();
    }

    float* Og = op + base + (long)q0*(BSZ*EMB);
    #pragma unroll
    for (int mi = 0; mi < 2; ++mi){
        float inv0 = 1.f/l_[mi][0], inv1 = 1.f/l_[mi][1];
        int m = w*32 + mi*16 + (lane>>2);
        #pragma unroll
        for (int ni = 0; ni < 8; ++ni){
            int d = ni*8 + 2*(lane&3);
            *(float2*)(Og + (long)m    *(BSZ*EMB) + d) = make_float2(o[mi][ni][0]*inv0, o[mi][ni][1]*inv0);
            *(float2*)(Og + (long)(m+8)*(BSZ*EMB) + d) = make_float2(o[mi][ni][2]*inv1, o[mi][ni][3]*inv1);
        }
        if ((lane & 3) == 0){
            gm[(long)hb*S_LEN + q0 + m]     = m_[mi][0];
            gm[(long)hb*S_LEN + q0 + m + 8] = m_[mi][1];
            gl[(long)hb*S_LEN + q0 + m]     = l_[mi][0];
            gl[(long)hb*S_LEN + q0 + m + 8] = l_[mi][1];
        }
    }
}

// ---------------------------------------------------------------------------
// attn_avg (round-13 exact): 256 thr, q-tile 128, k-tile 64, warps 4x2
// (MI=2, NI=4), double-buffered heads, log2-domain exp2.
// ---------------------------------------------------------------------------
__global__ __launch_bounds__(256)
void avg_attn(const float* __restrict__ qp, const float* __restrict__ kp,
              const float* __restrict__ gm, const float* __restrict__ gl,
              float* __restrict__ avg)
{
    extern __shared__ __align__(16) unsigned ASH[];
    constexpr int BUF = 128*72 + 64*72;
    const int tid = threadIdx.x, lane = tid&31, wid = tid>>5;
    const int wq = wid>>1, wk = wid&1;
    const int k0 = blockIdx.x*64, q0 = blockIdx.y*128, b = blockIdx.z;
    const int p = lane>>2;

    auto stage = [&](int h, int sel){
        unsigned* Qs = ASH + sel*BUF;
        unsigned* Ks = Qs + 128*72;
        const long base = (long)b*EMB + h*DH;
        #pragma unroll
        for (int j = 0; j < 8; ++j){
            int idx = tid + j*256;
            int r = idx>>4, c = (idx&15)*4;
            cpa16(&Qs[r*72 + c], qp + base + (long)(q0+r)*(BSZ*EMB) + c);
        }
        #pragma unroll
        for (int j = 0; j < 4; ++j){
            int idx = tid + j*256;
            int r = idx>>4, c = (idx&15)*4;
            cpa16(&Ks[r*72 + c], kp + base + (long)(k0+r)*(BSZ*EMB) + c);
        }
        asm volatile("cp.async.commit_group;\n");
    };

    float acc[2][4][4] = {};

    stage(0, 0);
    for (int h = 0; h < NH; ++h){
        if (h < NH-1){
            stage(h+1, (h+1)&1);
            asm volatile("cp.async.wait_group 1;\n");
        } else {
            asm volatile("cp.async.wait_group 0;\n");
        }
        __syncthreads();

        unsigned* Qs = ASH + (h&1)*BUF;
        unsigned* Ks = Qs + 128*72;

        float c_[2][4][4] = {};
        #pragma unroll
        for (int ks = 0; ks < 8; ++ks){
            int col = ks*8 + 2*(lane&3);
            unsigned a[2][4];
            #pragma unroll
            for (int mi = 0; mi < 2; ++mi){
                int m = wq*32 + mi*16 + p;
                uint2 u0 = *(const uint2*)&Qs[ m   *72 + col];
                uint2 u1 = *(const uint2*)&Qs[(m+8)*72 + col];
                a[mi][0] = u0.x; a[mi][1] = u1.x; a[mi][2] = u0.y; a[mi][3] = u1.y;
            }
            #pragma unroll
            for (int ni = 0; ni < 4; ++ni){
                int n = wk*32 + ni*8 + p;
                uint2 ub = *(const uint2*)&Ks[n*72 + col];
                unsigned bf[2] = { ub.x, ub.y };
                mma8(c_[0][ni], a[0], bf);
                mma8(c_[1][ni], a[1], bf);
            }
        }

        const int hb = b*NH + h;
        #pragma unroll
        for (int mi = 0; mi < 2; ++mi){
            int r0 = q0 + wq*32 + mi*16 + p;
            float e0 = gm[(long)hb*S_LEN + r0    ] + __log2f(gl[(long)hb*S_LEN + r0    ]) + 4.0f;
            float e1 = gm[(long)hb*S_LEN + r0 + 8] + __log2f(gl[(long)hb*S_LEN + r0 + 8]) + 4.0f;
            #pragma unroll
            for (int ni = 0; ni < 4; ++ni){
                acc[mi][ni][0] += exp2f(c_[mi][ni][0] - e0);
                acc[mi][ni][1] += exp2f(c_[mi][ni][1] - e0);
                acc[mi][ni][2] += exp2f(c_[mi][ni][2] - e1);
                acc[mi][ni][3] += exp2f(c_[mi][ni][3] - e1);
            }
        }
        __syncthreads();
    }

    float* out = avg + (long)b*S2;
    #pragma unroll
    for (int mi = 0; mi < 2; ++mi){
        int r0 = q0 + wq*32 + mi*16 + p;
        #pragma unroll
        for (int ni = 0; ni < 4; ++ni){
            int kc = k0 + wk*32 + ni*8 + 2*(lane&3);
            *(float2*)(out + (long)r0    *S_LEN + kc) = make_float2(acc[mi][ni][0], acc[mi][ni][1]);
            *(float2*)(out + (long)(r0+8)*S_LEN + kc) = make_float2(acc[mi][ni][2], acc[mi][ni][3]);
        }
    }
}

// ---------------------------------------------------------------------------
extern "C" void kernel_launch(void* const* d_in, const int* in_sizes, int n_in,
                              void* d_out, int out_size)
{
    const float* query = (const float*)d_in[0];
    const float* key   = (const float*)d_in[1];
    const float* value = (const float*)d_in[2];
    const float* q_w = (const float*)d_in[3];
    const float* q_b = (const float*)d_in[4];
    const float* k_w = (const float*)d_in[5];
    const float* k_b = (const float*)d_in[6];
    const float* v_w = (const float*)d_in[7];
    const float* v_b = (const float*)d_in[8];
    const float* out_w = (const float*)d_in[9];
    const float* out_b = (const float*)d_in[10];

    float *qp, *kp, *vp, *op, *gm, *gl;
    __half* vh;
    cudaGetSymbolAddress((void**)&qp, g_Qp);
    cudaGetSymbolAddress((void**)&kp, g_Kp);
    cudaGetSymbolAddress((void**)&vp, g_Vp);
    cudaGetSymbolAddress((void**)&vh, g_Vh);
    cudaGetSymbolAddress((void**)&op, g_O);
    cudaGetSymbolAddress((void**)&gm, g_m);
    cudaGetSymbolAddress((void**)&gl, g_l);

    float* Z = (float*)d_out;
    float* attn_avg = (float*)d_out + (long)MROWS*EMB;

    static cudaStream_t s2 = nullptr;
    static cudaEvent_t evFork = nullptr, evJoin = nullptr;
    if (!s2){
        cudaStreamCreateWithFlags(&s2, cudaStreamNonBlocking);
        cudaEventCreateWithFlags(&evFork, cudaEventDisableTiming);
        cudaEventCreateWithFlags(&evJoin, cudaEventDisableTiming);
        cudaFuncSetAttribute(avg_attn,  cudaFuncAttributeMaxDynamicSharedMemorySize, 110592);
        cudaFuncSetAttribute(qkv_proj,  cudaFuncAttributeMaxDynamicSharedMemorySize, 81920);
        cudaFuncSetAttribute(out_proj,  cudaFuncAttributeMaxDynamicSharedMemorySize, 81920);
    }

    // 1) Q/K/V projections (Q pre-scaled into log2 domain)
    dim3 gqkv(EMB/128, MROWS/128, 3);
    qkv_proj<<<gqkv, 256, 81920>>>(query, key, value, q_w, q_b, k_w, k_b, v_w, v_b, qp, kp, vp);

    // 1b) V -> fp16 transposed
    dim3 gvt(S_LEN/64, NHEADS, 1);
    v_transpose<<<gvt, 256>>>(vp, (unsigned*)vh);

    // 2) Flash attention
    dim3 gfa(NHEADS, S_LEN/128, 1);
    flash_attn<<<gfa, 128>>>(qp, kp, vh, op, gm, gl);

    // fork: out_proj concurrent with avg_attn
    cudaEventRecord(evFork, 0);
    cudaStreamWaitEvent(s2, evFork, 0);

    dim3 gop(EMB/128, MROWS/128, 1);
    out_proj<<<gop, 256, 81920, s2>>>(op, out_w, out_b, Z);
    cudaEventRecord(evJoin, s2);

    dim3 gav(S_LEN/64, S_LEN/128, BSZ);
    avg_attn<<<gav, 256, 110592>>>(qp, kp, gm, gl, attn_avg);

    cudaStreamWaitEvent(0, evJoin, 0);
}

// round 15
// speedup vs baseline: 1.3053x; 1.1937x over previous
#include <cuda_runtime.h>
#include <cuda_fp16.h>

#define S_LEN 2048
#define BSZ   2
#define EMB   1024
#define NH    16
#define DH    64
#define MROWS 4096
#define NHEADS 32
#define S2 ((long)S_LEN*S_LEN)
#define LOG2E 1.4426950408889634f

// Scratch (__device__ globals per alloc-free rule)
__device__ __half g_Qph[(size_t)MROWS*EMB]; // fp16, half2-word pair-permuted, pre-scaled 0.125*log2e
__device__ __half g_Kph[(size_t)MROWS*EMB]; // fp16, half2-word pair-permuted
__device__ float  g_Vp [MROWS*EMB];         // fp32, normal layout (v_transpose input)
__device__ __half g_Vh [(size_t)MROWS*EMB]; // transposed fp16: row (hb*64+d), col s
__device__ float  g_O  [MROWS*EMB];
__device__ float  g_m  [NHEADS*S_LEN];      // log2-domain running max
__device__ float  g_l  [NHEADS*S_LEN];      // linear sum of exp2(s - m)

__device__ __forceinline__ unsigned f2tf(float f){
    unsigned u; asm("cvt.rna.tf32.f32 %0, %1;" : "=r"(u) : "f"(f)); return u;
}
__device__ __forceinline__ unsigned packh2(float lo, float hi){
    __half2 h = __floats2half2_rn(lo, hi);
    return *(unsigned*)&h;
}
__device__ __forceinline__ void mma8(float* c, const unsigned* a, const unsigned* b){
    asm volatile("mma.sync.aligned.m16n8k8.row.col.f32.tf32.tf32.f32 "
      "{%0,%1,%2,%3}, {%4,%5,%6,%7}, {%8,%9}, {%0,%1,%2,%3};\n"
      : "+f"(c[0]), "+f"(c[1]), "+f"(c[2]), "+f"(c[3])
      : "r"(a[0]), "r"(a[1]), "r"(a[2]), "r"(a[3]), "r"(b[0]), "r"(b[1]));
}
__device__ __forceinline__ void mma16f16(float* c, const unsigned* a, unsigned b0, unsigned b1){
    asm volatile("mma.sync.aligned.m16n8k16.row.col.f32.f16.f16.f32 "
      "{%0,%1,%2,%3}, {%4,%5,%6,%7}, {%8,%9}, {%0,%1,%2,%3};\n"
      : "+f"(c[0]), "+f"(c[1]), "+f"(c[2]), "+f"(c[3])
      : "r"(a[0]), "r"(a[1]), "r"(a[2]), "r"(a[3]), "r"(b0), "r"(b1));
}
__device__ __forceinline__ void cpa16(void* dst, const void* src){
    unsigned d = (unsigned)__cvta_generic_to_shared(dst);
    asm volatile("cp.async.cg.shared.global [%0], [%1], 16;\n" :: "r"(d), "l"(src));
}

// ---------------------------------------------------------------------------
// TN tf32 GEMM body (round-14 proven): BM=128, BN=128, BK=32, WM=64 (MI=4),
// WN=32 (NI=4), 8 warps, pair-group staging stride 40, LDS.64 fragments.
// Dynamic smem 81920 B.
// permOut: write fp16 into Ch, half2-word pair-permuted (for fp16 MMA frags).
// ---------------------------------------------------------------------------
__device__ __forceinline__
void gemm_body(const float* __restrict__ A, int lda,
               const float* __restrict__ B, int ldb,
               float* __restrict__ C, __half* __restrict__ Ch, int ldc,
               const float* __restrict__ bias, float scale, int K,
               int m0, int n0, bool permOut, unsigned* SM)
{
    constexpr int ST = 40;
    unsigned* const As = SM;             // [2][128][40]
    unsigned* const Bs = SM + 2*128*ST;  // [2][128][40]

    const int tid  = threadIdx.x;
    const int lane = tid & 31, wid = tid >> 5;
    const int wm = wid >> 2, wn = wid & 3;

    float acc[4][4][4] = {};
    float4 ra[2][2], rb[2][2];

    auto ldtiles = [&](int k0){
        #pragma unroll
        for (int i = 0; i < 2; ++i){
            int g = tid + i*256;
            int r = g>>2, c8 = (g&3)*8;
            ra[i][0] = *(const float4*)(A + (long)(m0+r)*lda + k0 + c8);
            ra[i][1] = *(const float4*)(A + (long)(m0+r)*lda + k0 + c8 + 4);
            rb[i][0] = *(const float4*)(B + (long)(n0+r)*ldb + k0 + c8);
            rb[i][1] = *(const float4*)(B + (long)(n0+r)*ldb + k0 + c8 + 4);
        }
    };
    auto sttiles = [&](int buf){
        #pragma unroll
        for (int i = 0; i < 2; ++i){
            int g = tid + i*256;
            int r = g>>2, c8 = (g&3)*8;
            const int sw = r & 1;
            uint4 u0 = { f2tf(ra[i][0].x), f2tf(ra[i][1].x), f2tf(ra[i][0].y), f2tf(ra[i][1].y) };
            uint4 u1 = { f2tf(ra[i][0].z), f2tf(ra[i][1].z), f2tf(ra[i][0].w), f2tf(ra[i][1].w) };
            unsigned* p = &As[buf*128*ST + r*ST + c8];
            *(uint4*)(p + (sw?4:0)) = sw ? u1 : u0;
            *(uint4*)(p + (sw?0:4)) = sw ? u0 : u1;
            uint4 v0 = { f2tf(rb[i][0].x), f2tf(rb[i][1].x), f2tf(rb[i][0].y), f2tf(rb[i][1].y) };
            uint4 v1 = { f2tf(rb[i][0].z), f2tf(rb[i][1].z), f2tf(rb[i][0].w), f2tf(rb[i][1].w) };
            unsigned* q = &Bs[buf*128*ST + r*ST + c8];
            *(uint4*)(q + (sw?4:0)) = sw ? v1 : v0;
            *(uint4*)(q + (sw?0:4)) = sw ? v0 : v1;
        }
    };
    auto compute = [&](int buf){
        const int p = lane >> 2;
        #pragma unroll
        for (int ks = 0; ks < 4; ++ks){
            const int col = ks*8 + 2*(lane&3);
            unsigned af[4][4], bf[4][2];
            #pragma unroll
            for (int mi = 0; mi < 4; ++mi){
                int m = wm*64 + mi*16 + p;
                uint2 u0 = *(const uint2*)&As[buf*128*ST +  m   *ST + col];
                uint2 u1 = *(const uint2*)&As[buf*128*ST + (m+8)*ST + col];
                af[mi][0] = u0.x; af[mi][1] = u1.x; af[mi][2] = u0.y; af[mi][3] = u1.y;
            }
            #pragma unroll
            for (int ni = 0; ni < 4; ++ni){
                int n = wn*32 + ni*8 + p;
                uint2 ub = *(const uint2*)&Bs[buf*128*ST + n*ST + col];
                bf[ni][0] = ub.x; bf[ni][1] = ub.y;
            }
            #pragma unroll
            for (int mi = 0; mi < 4; ++mi)
                #pragma unroll
                for (int ni = 0; ni < 4; ++ni)
                    mma8(acc[mi][ni], af[mi], bf[ni]);
        }
    };

    ldtiles(0); sttiles(0); __syncthreads();
    const int nk = K/32;
    for (int t = 1; t < nk; ++t){
        ldtiles(t*32);
        compute((t-1)&1);
        sttiles(t&1);
        __syncthreads();
    }
    compute((nk-1)&1);

    #pragma unroll
    for (int mi = 0; mi < 4; ++mi){
        #pragma unroll
        for (int ni = 0; ni < 4; ++ni){
            int m = m0 + wm*64 + mi*16 + (lane>>2);
            int n = n0 + wn*32 + ni*8 + 2*(lane&3);
            float v0 = acc[mi][ni][0], v1 = acc[mi][ni][1];
            float v2 = acc[mi][ni][2], v3 = acc[mi][ni][3];
            float b0 = bias[n], b1 = bias[n+1];
            v0 = (v0+b0)*scale; v1 = (v1+b1)*scale;
            v2 = (v2+b0)*scale; v3 = (v3+b1)*scale;
            if (permOut){
                // half2 word index, pair-permuted within 8-word (16-half) groups
                int W  = n >> 1;
                int pw = (W & ~7) | ((W&3)<<1) | ((W>>2)&1);
                *(unsigned*)&Ch[(long)m    *ldc + 2*pw] = packh2(v0, v1);
                *(unsigned*)&Ch[(long)(m+8)*ldc + 2*pw] = packh2(v2, v3);
            } else {
                *(float2*)(C + (long)m    *ldc + n) = make_float2(v0, v1);
                *(float2*)(C + (long)(m+8)*ldc + n) = make_float2(v2, v3);
            }
        }
    }
}

// Merged Q/K/V projections. Q scaled by 0.125*log2e. Q,K -> fp16 permuted.
__global__ __launch_bounds__(256)
void qkv_proj(const float* __restrict__ q, const float* __restrict__ k, const float* __restrict__ v,
              const float* __restrict__ qw, const float* __restrict__ qb,
              const float* __restrict__ kw, const float* __restrict__ kb,
              const float* __restrict__ vw, const float* __restrict__ vb,
              __half* __restrict__ qph, __half* __restrict__ kph, float* __restrict__ vp)
{
    extern __shared__ __align__(16) unsigned GSM[];
    const int z = blockIdx.z;
    const float* A  = (z==0)? q  : (z==1)? k  : v;
    const float* W  = (z==0)? qw : (z==1)? kw : vw;
    const float* bi = (z==0)? qb : (z==1)? kb : vb;
    __half* Ch = (z==0)? qph : kph;
    const float scale = (z==0)? 0.125f*LOG2E : 1.0f;
    gemm_body(A, EMB, W, EMB, vp, Ch, EMB, bi, scale, EMB,
              blockIdx.y*128, blockIdx.x*128, z<2, GSM);
}

__global__ __launch_bounds__(256)
void out_proj(const float* __restrict__ A, const float* __restrict__ W,
              const float* __restrict__ bi, float* __restrict__ C)
{
    extern __shared__ __align__(16) unsigned GSM[];
    gemm_body(A, EMB, W, EMB, C, nullptr, EMB, bi, 1.0f, EMB,
              blockIdx.y*128, blockIdx.x*128, false, GSM);
}

// ---------------------------------------------------------------------------
// V transpose+convert: vp fp32 -> vh half [hb*64+d][s].
// ---------------------------------------------------------------------------
__global__ __launch_bounds__(256)
void v_transpose(const float* __restrict__ vp, unsigned* __restrict__ vh2)
{
    __shared__ float T[64][65];
    const int tid = threadIdx.x;
    const int hb = blockIdx.y, h = hb&15, b = hb>>4;
    const int s0 = blockIdx.x*64;

    #pragma unroll
    for (int i = 0; i < 4; ++i){
        int idx = tid + i*256;
        int si = idx>>4, d4 = (idx&15)*4;
        float4 u = *(const float4*)(vp + (long)((s0+si)*2 + b)*EMB + h*64 + d4);
        T[si][d4+0]=u.x; T[si][d4+1]=u.y; T[si][d4+2]=u.z; T[si][d4+3]=u.w;
    }
    __syncthreads();

    #pragma unroll
    for (int j = 0; j < 8; ++j){
        int w = tid + j*256;
        int d = w>>5, sp = w&31;
        unsigned val = packh2(T[2*sp][d], T[2*sp+1][d]);
        vh2[(long)(hb*64 + d)*1024 + (s0>>1) + sp] = val;
    }
}

// ---------------------------------------------------------------------------
// Flash attention: q-tile 128, 4 warps (MI=2), k-tiles 32 double-buffered.
// fp16 QK^T (m16n8k16, log2-domain scores) + fp16 PV. Q/K arrive as fp16
// half2-word pair-permuted -> LDS.64 fragments, stride 40.
// ---------------------------------------------------------------------------
__global__ __launch_bounds__(128)
void flash_attn(const __half* __restrict__ qp, const __half* __restrict__ kp,
                const __half* __restrict__ vh, float* __restrict__ op,
                float* __restrict__ gm, float* __restrict__ gl)
{
    __shared__ __align__(16) unsigned SU[5120];
    const int tid = threadIdx.x, lane = tid&31, w = tid>>5;
    const int hb = blockIdx.x, h = hb&15, b = hb>>4;
    const int q0 = blockIdx.y*128;
    const long baseh = (long)b*EMB + h*DH;
    const __half* Qg = qp + baseh + (long)q0*(BSZ*EMB);
    const __half* Kg = kp + baseh;
    const __half* Vgh = vh + (long)hb*64*2048;

    // stage Q (fp16 permuted): 128 rows x 8 16B-chunks
    for (int i = tid; i < 1024; i += 128){
        int r = i>>3, c = i&7;
        cpa16(&SU[r*40 + c*4], Qg + (long)r*(BSZ*EMB) + c*8);
    }
    asm volatile("cp.async.commit_group;\n");
    asm volatile("cp.async.wait_group 0;\n");
    __syncthreads();

    unsigned Qa[4][2][4];
    {
        const int p = lane>>2, q2 = 2*(lane&3);
        #pragma unroll
        for (int ks = 0; ks < 4; ++ks)
            #pragma unroll
            for (int mi = 0; mi < 2; ++mi){
                int m = w*32 + mi*16 + p;
                int col = ks*8 + q2;
                uint2 u0 = *(const uint2*)&SU[ m   *40 + col];
                uint2 u1 = *(const uint2*)&SU[(m+8)*40 + col];
                Qa[ks][mi][0] = u0.x; Qa[ks][mi][1] = u1.x;
                Qa[ks][mi][2] = u0.y; Qa[ks][mi][3] = u1.y;
            }
    }
    __syncthreads();

    unsigned* const Kb0 = SU;
    unsigned* const Kb1 = SU + 1280;   // 32*40
    unsigned* const Vh0 = SU + 2560;
    unsigned* const Vh1 = SU + 3840;   // 2560 + 64*20

    auto load_kv = [&](int kt, int sel){
        unsigned* Kb = sel ? Kb1 : Kb0;
        unsigned* Vb = sel ? Vh1 : Vh0;
        const long r0 = (long)kt*32;
        #pragma unroll
        for (int j = 0; j < 2; ++j){
            int idx = tid + j*128;            // K: 256 16B units (32 rows x 8)
            int r = idx>>3, c = idx&7;
            cpa16(&Kb[r*40 + c*4], Kg + (r0+r)*(BSZ*EMB) + c*8);
        }
        #pragma unroll
        for (int j = 0; j < 2; ++j){
            int u = tid + j*128;              // V: 256 16B units
            int d = u>>2, qc = u&3;
            cpa16(&Vb[d*20 + qc*4], Vgh + (long)d*2048 + kt*32 + qc*8);
        }
    };

    float m_[2][2] = {{-1e30f,-1e30f},{-1e30f,-1e30f}};
    float l_[2][2] = {};
    float o[2][8][4] = {};

    load_kv(0, 0);
    asm volatile("cp.async.commit_group;\n");

    for (int t = 0; t < 64; ++t){
        if (t < 63){
            load_kv(t+1, (t+1)&1);
            asm volatile("cp.async.commit_group;\n");
            asm volatile("cp.async.wait_group 1;\n");
        } else {
            asm volatile("cp.async.wait_group 0;\n");
        }
        __syncthreads();

        unsigned* Kb = (t&1) ? Kb1 : Kb0;
        unsigned* Vb = (t&1) ? Vh1 : Vh0;

        // S = Q K^T in fp16 m16n8k16 (4 k-steps)
        float c_[2][4][4] = {};
        #pragma unroll
        for (int ks = 0; ks < 4; ++ks){
            const int col = ks*8 + 2*(lane&3);
            unsigned bf[4][2];
            #pragma unroll
            for (int ni = 0; ni < 4; ++ni){
                int n = ni*8 + (lane>>2);
                uint2 u = *(const uint2*)&Kb[n*40 + col];
                bf[ni][0] = u.x; bf[ni][1] = u.y;
            }
            #pragma unroll
            for (int mi = 0; mi < 2; ++mi)
                #pragma unroll
                for (int ni = 0; ni < 4; ++ni)
                    mma16f16(c_[mi][ni], Qa[ks][mi], bf[ni][0], bf[ni][1]);
        }

        // online softmax (log2-domain) with rescale-skip
        #pragma unroll
        for (int mi = 0; mi < 2; ++mi){
            float mx0 = -1e30f, mx1 = -1e30f;
            #pragma unroll
            for (int ni = 0; ni < 4; ++ni){
                mx0 = fmaxf(mx0, fmaxf(c_[mi][ni][0], c_[mi][ni][1]));
                mx1 = fmaxf(mx1, fmaxf(c_[mi][ni][2], c_[mi][ni][3]));
            }
            mx0 = fmaxf(mx0, __shfl_xor_sync(0xffffffffu, mx0, 1));
            mx0 = fmaxf(mx0, __shfl_xor_sync(0xffffffffu, mx0, 2));
            mx1 = fmaxf(mx1, __shfl_xor_sync(0xffffffffu, mx1, 1));
            mx1 = fmaxf(mx1, __shfl_xor_sync(0xffffffffu, mx1, 2));
            float mn0 = fmaxf(m_[mi][0], mx0), mn1 = fmaxf(m_[mi][1], mx1);
            if (!__all_sync(0xffffffffu, (mn0 == m_[mi][0]) & (mn1 == m_[mi][1]))){
                float f0 = exp2f(m_[mi][0] - mn0), f1 = exp2f(m_[mi][1] - mn1);
                l_[mi][0] *= f0; l_[mi][1] *= f1;
                #pragma unroll
                for (int ni = 0; ni < 8; ++ni){
                    o[mi][ni][0]*=f0; o[mi][ni][1]*=f0;
                    o[mi][ni][2]*=f1; o[mi][ni][3]*=f1;
                }
                m_[mi][0] = mn0; m_[mi][1] = mn1;
            }
            float s0 = 0.f, s1 = 0.f;
            #pragma unroll
            for (int ni = 0; ni < 4; ++ni){
                c_[mi][ni][0] = exp2f(c_[mi][ni][0]-m_[mi][0]);
                c_[mi][ni][1] = exp2f(c_[mi][ni][1]-m_[mi][0]);
                c_[mi][ni][2] = exp2f(c_[mi][ni][2]-m_[mi][1]);
                c_[mi][ni][3] = exp2f(c_[mi][ni][3]-m_[mi][1]);
                s0 += c_[mi][ni][0]+c_[mi][ni][1];
                s1 += c_[mi][ni][2]+c_[mi][ni][3];
            }
            s0 += __shfl_xor_sync(0xffffffffu, s0, 1);
            s0 += __shfl_xor_sync(0xffffffffu, s0, 2);
            s1 += __shfl_xor_sync(0xffffffffu, s1, 1);
            s1 += __shfl_xor_sync(0xffffffffu, s1, 2);
            l_[mi][0] += s0; l_[mi][1] += s1;
        }

        // P @ V fp16 (no shuffles)
        #pragma unroll
        for (int j = 0; j < 2; ++j){
            unsigned a[2][4];
            #pragma unroll
            for (int mi = 0; mi < 2; ++mi){
                a[mi][0] = packh2(c_[mi][2*j  ][0], c_[mi][2*j  ][1]);
                a[mi][1] = packh2(c_[mi][2*j  ][2], c_[mi][2*j  ][3]);
                a[mi][2] = packh2(c_[mi][2*j+1][0], c_[mi][2*j+1][1]);
                a[mi][3] = packh2(c_[mi][2*j+1][2], c_[mi][2*j+1][3]);
            }
            #pragma unroll
            for (int ni = 0; ni < 8; ++ni){
                int n = ni*8 + (lane>>2);
                unsigned b0 = Vb[n*20 + 8*j + (lane&3)];
                unsigned b1 = Vb[n*20 + 8*j + (lane&3) + 4];
                mma16f16(o[0][ni], a[0], b0, b1);
                mma16f16(o[1][ni], a[1], b0, b1);
            }
        }
        __syncthreads();
    }

    float* Og = op + baseh + (long)q0*(BSZ*EMB);
    #pragma unroll
    for (int mi = 0; mi < 2; ++mi){
        float inv0 = 1.f/l_[mi][0], inv1 = 1.f/l_[mi][1];
        int m = w*32 + mi*16 + (lane>>2);
        #pragma unroll
        for (int ni = 0; ni < 8; ++ni){
            int d = ni*8 + 2*(lane&3);
            *(float2*)(Og + (long)m    *(BSZ*EMB) + d) = make_float2(o[mi][ni][0]*inv0, o[mi][ni][1]*inv0);
            *(float2*)(Og + (long)(m+8)*(BSZ*EMB) + d) = make_float2(o[mi][ni][2]*inv1, o[mi][ni][3]*inv1);
        }
        if ((lane & 3) == 0){
            gm[(long)hb*S_LEN + q0 + m]     = m_[mi][0];
            gm[(long)hb*S_LEN + q0 + m + 8] = m_[mi][1];
            gl[(long)hb*S_LEN + q0 + m]     = l_[mi][0];
            gl[(long)hb*S_LEN + q0 + m + 8] = l_[mi][1];
        }
    }
}

// ---------------------------------------------------------------------------
// attn_avg: 256 thr, q-tile 128, k-tile 64, warps 4x2 (MI=2, NI=4),
// double-buffered heads, fp16 m16n8k16 scores, log2-domain exp2.
// Dynamic smem: 2*(128*40 + 64*40)*4 = 61440 B.
// ---------------------------------------------------------------------------
__global__ __launch_bounds__(256)
void avg_attn(const __half* __restrict__ qp, const __half* __restrict__ kp,
              const float* __restrict__ gm, const float* __restrict__ gl,
              float* __restrict__ avg)
{
    extern __shared__ __align__(16) unsigned ASH[];
    constexpr int BUF = 128*40 + 64*40;   // 7680 words
    const int tid = threadIdx.x, lane = tid&31, wid = tid>>5;
    const int wq = wid>>1, wk = wid&1;
    const int k0 = blockIdx.x*64, q0 = blockIdx.y*128, b = blockIdx.z;
    const int p = lane>>2;

    auto stage = [&](int h, int sel){
        unsigned* Qs = ASH + sel*BUF;
        unsigned* Ks = Qs + 128*40;
        const long baseh = (long)b*EMB + h*DH;
        #pragma unroll
        for (int j = 0; j < 4; ++j){
            int idx = tid + j*256;            // Q: 1024 16B units
            int r = idx>>3, c = idx&7;
            cpa16(&Qs[r*40 + c*4], qp + baseh + (long)(q0+r)*(BSZ*EMB) + c*8);
        }
        #pragma unroll
        for (int j = 0; j < 2; ++j){
            int idx = tid + j*256;            // K: 512 16B units
            int r = idx>>3, c = idx&7;
            cpa16(&Ks[r*40 + c*4], kp + baseh + (long)(k0+r)*(BSZ*EMB) + c*8);
        }
        asm volatile("cp.async.commit_group;\n");
    };

    float acc[2][4][4] = {};

    stage(0, 0);
    for (int h = 0; h < NH; ++h){
        if (h < NH-1){
            stage(h+1, (h+1)&1);
            asm volatile("cp.async.wait_group 1;\n");
        } else {
            asm volatile("cp.async.wait_group 0;\n");
        }
        __syncthreads();

        unsigned* Qs = ASH + (h&1)*BUF;
        unsigned* Ks = Qs + 128*40;

        float c_[2][4][4] = {};
        #pragma unroll
        for (int ks = 0; ks < 4; ++ks){
            const int col = ks*8 + 2*(lane&3);
            unsigned a[2][4];
            #pragma unroll
            for (int mi = 0; mi < 2; ++mi){
                int m = wq*32 + mi*16 + p;
                uint2 u0 = *(const uint2*)&Qs[ m   *40 + col];
                uint2 u1 = *(const uint2*)&Qs[(m+8)*40 + col];
                a[mi][0] = u0.x; a[mi][1] = u1.x; a[mi][2] = u0.y; a[mi][3] = u1.y;
            }
            #pragma unroll
            for (int ni = 0; ni < 4; ++ni){
                int n = wk*32 + ni*8 + p;
                uint2 ub = *(const uint2*)&Ks[n*40 + col];
                mma16f16(c_[0][ni], a[0], ub.x, ub.y);
                mma16f16(c_[1][ni], a[1], ub.x, ub.y);
            }
        }

        const int hb = b*NH + h;
        #pragma unroll
        for (int mi = 0; mi < 2; ++mi){
            int r0 = q0 + wq*32 + mi*16 + p;
            float e0 = gm[(long)hb*S_LEN + r0    ] + __log2f(gl[(long)hb*S_LEN + r0    ]) + 4.0f;
            float e1 = gm[(long)hb*S_LEN + r0 + 8] + __log2f(gl[(long)hb*S_LEN + r0 + 8]) + 4.0f;
            #pragma unroll
            for (int ni = 0; ni < 4; ++ni){
                acc[mi][ni][0] += exp2f(c_[mi][ni][0] - e0);
                acc[mi][ni][1] += exp2f(c_[mi][ni][1] - e0);
                acc[mi][ni][2] += exp2f(c_[mi][ni][2] - e1);
                acc[mi][ni][3] += exp2f(c_[mi][ni][3] - e1);
            }
        }
        __syncthreads();
    }

    float* out = avg + (long)b*S2;
    #pragma unroll
    for (int mi = 0; mi < 2; ++mi){
        int r0 = q0 + wq*32 + mi*16 + p;
        #pragma unroll
        for (int ni = 0; ni < 4; ++ni){
            int kc = k0 + wk*32 + ni*8 + 2*(lane&3);
            *(float2*)(out + (long)r0    *S_LEN + kc) = make_float2(acc[mi][ni][0], acc[mi][ni][1]);
            *(float2*)(out + (long)(r0+8)*S_LEN + kc) = make_float2(acc[mi][ni][2], acc[mi][ni][3]);
        }
    }
}

// ---------------------------------------------------------------------------
extern "C" void kernel_launch(void* const* d_in, const int* in_sizes, int n_in,
                              void* d_out, int out_size)
{
    const float* query = (const float*)d_in[0];
    const float* key   = (const float*)d_in[1];
    const float* value = (const float*)d_in[2];
    const float* q_w = (const float*)d_in[3];
    const float* q_b = (const float*)d_in[4];
    const float* k_w = (const float*)d_in[5];
    const float* k_b = (const float*)d_in[6];
    const float* v_w = (const float*)d_in[7];
    const float* v_b = (const float*)d_in[8];
    const float* out_w = (const float*)d_in[9];
    const float* out_b = (const float*)d_in[10];

    float *vp, *op, *gm, *gl;
    __half *qph, *kph, *vh;
    cudaGetSymbolAddress((void**)&qph, g_Qph);
    cudaGetSymbolAddress((void**)&kph, g_Kph);
    cudaGetSymbolAddress((void**)&vp,  g_Vp);
    cudaGetSymbolAddress((void**)&vh,  g_Vh);
    cudaGetSymbolAddress((void**)&op,  g_O);
    cudaGetSymbolAddress((void**)&gm,  g_m);
    cudaGetSymbolAddress((void**)&gl,  g_l);

    float* Z = (float*)d_out;
    float* attn_avg = (float*)d_out + (long)MROWS*EMB;

    static cudaStream_t s2 = nullptr;
    static cudaEvent_t evFork = nullptr, evJoin = nullptr;
    if (!s2){
        cudaStreamCreateWithFlags(&s2, cudaStreamNonBlocking);
        cudaEventCreateWithFlags(&evFork, cudaEventDisableTiming);
        cudaEventCreateWithFlags(&evJoin, cudaEventDisableTiming);
        cudaFuncSetAttribute(avg_attn,  cudaFuncAttributeMaxDynamicSharedMemorySize, 61440);
        cudaFuncSetAttribute(qkv_proj,  cudaFuncAttributeMaxDynamicSharedMemorySize, 81920);
        cudaFuncSetAttribute(out_proj,  cudaFuncAttributeMaxDynamicSharedMemorySize, 81920);
    }

    // 1) Q/K/V projections (Q,K -> fp16 permuted; Q pre-scaled log2-domain)
    dim3 gqkv(EMB/128, MROWS/128, 3);
    qkv_proj<<<gqkv, 256, 81920>>>(query, key, value, q_w, q_b, k_w, k_b, v_w, v_b, qph, kph, vp);

    // 1b) V -> fp16 transposed
    dim3 gvt(S_LEN/64, NHEADS, 1);
    v_transpose<<<gvt, 256>>>(vp, (unsigned*)vh);

    // 2) Flash attention (fp16 scores + fp16 PV)
    dim3 gfa(NHEADS, S_LEN/128, 1);
    flash_attn<<<gfa, 128>>>(qph, kph, vh, op, gm, gl);

    // fork: out_proj concurrent with avg_attn
    cudaEventRecord(evFork, 0);
    cudaStreamWaitEvent(s2, evFork, 0);

    dim3 gop(EMB/128, MROWS/128, 1);
    out_proj<<<gop, 256, 81920, s2>>>(op, out_w, out_b, Z);
    cudaEventRecord(evJoin, s2);

    dim3 gav(S_LEN/64, S_LEN/128, BSZ);
    avg_attn<<<gav, 256, 61440>>>(qph, kph, gm, gl, attn_avg);

    cudaStreamWaitEvent(0, evJoin, 0);
}

// round 16
// speedup vs baseline: 1.4972x; 1.1470x over previous
#include <cuda_runtime.h>
#include <cuda_fp16.h>

#define S_LEN 2048
#define BSZ   2
#define EMB   1024
#define NH    16
#define DH    64
#define MROWS 4096
#define NHEADS 32
#define S2 ((long)S_LEN*S_LEN)
#define LOG2E 1.4426950408889634f

// Scratch (__device__ globals per alloc-free rule)
__device__ __half g_Qph[(size_t)MROWS*EMB]; // fp16, half2-word pair-permuted, pre-scaled 0.125*log2e
__device__ __half g_Kph[(size_t)MROWS*EMB]; // fp16, half2-word pair-permuted
__device__ float  g_Vp [MROWS*EMB];         // fp32, normal layout (v_transpose input)
__device__ __half g_Vh [(size_t)MROWS*EMB]; // transposed fp16: row (hb*64+d), col s
__device__ float  g_O  [MROWS*EMB];
__device__ float  g_m  [NHEADS*S_LEN];      // log2-domain running max
__device__ float  g_l  [NHEADS*S_LEN];      // linear sum of exp2(s - m)

__device__ __forceinline__ unsigned packh2(float lo, float hi){
    __half2 h = __floats2half2_rn(lo, hi);
    return *(unsigned*)&h;
}
__device__ __forceinline__ void mma16f16(float* c, const unsigned* a, unsigned b0, unsigned b1){
    asm volatile("mma.sync.aligned.m16n8k16.row.col.f32.f16.f16.f32 "
      "{%0,%1,%2,%3}, {%4,%5,%6,%7}, {%8,%9}, {%0,%1,%2,%3};\n"
      : "+f"(c[0]), "+f"(c[1]), "+f"(c[2]), "+f"(c[3])
      : "r"(a[0]), "r"(a[1]), "r"(a[2]), "r"(a[3]), "r"(b0), "r"(b1));
}
__device__ __forceinline__ void cpa16(void* dst, const void* src){
    unsigned d = (unsigned)__cvta_generic_to_shared(dst);
    asm volatile("cp.async.cg.shared.global [%0], [%1], 16;\n" :: "r"(d), "l"(src));
}

// ---------------------------------------------------------------------------
// TN fp16 GEMM body: BM=128, BN=128, BK=32 (2 k16 atoms), WM=64 (MI=4),
// WN=32 (NI=4), 8 warps, m16n8k16 MMA, fp32 accumulate.
// Smem: rows hold 16 half2 words, pair-permuted within 8-word atom groups,
// stride 24 words (fragment LDS.64 conflict-free; STS.128 conflict-free via
// odd-row instruction-pairing swap). Dynamic smem 2*(128+128)*24*4 = 49152 B.
// permOut: write fp16 into Ch, half2-word pair-permuted (flash/avg format).
// ---------------------------------------------------------------------------
__device__ __forceinline__
void gemm_body(const float* __restrict__ A, int lda,
               const float* __restrict__ B, int ldb,
               float* __restrict__ C, __half* __restrict__ Ch, int ldc,
               const float* __restrict__ bias, float scale, int K,
               int m0, int n0, bool permOut, unsigned* SM)
{
    constexpr int ST = 24;
    unsigned* const As = SM;             // [2][128][24]
    unsigned* const Bs = SM + 2*128*ST;  // [2][128][24]

    const int tid  = threadIdx.x;
    const int lane = tid & 31, wid = tid >> 5;
    const int wm = wid >> 2, wn = wid & 3;
    const int r  = tid >> 1, at = tid & 1;   // staging: row, k16-atom
    const int sw = r & 1;

    float acc[4][4][4] = {};
    float4 ra[4], rb[4];

    auto ldtiles = [&](int k0){
        const float* Ap = A + (long)(m0+r)*lda + k0 + at*16;
        const float* Bp = B + (long)(n0+r)*ldb + k0 + at*16;
        #pragma unroll
        for (int c = 0; c < 4; ++c){
            ra[c] = *(const float4*)(Ap + c*4);
            rb[c] = *(const float4*)(Bp + c*4);
        }
    };
    auto sttiles = [&](int buf){
        // permuted order: [W0,W4,W1,W5 | W2,W6,W3,W7], Wi = pack(f2i, f2i+1)
        uint4 u0 = { packh2(ra[0].x,ra[0].y), packh2(ra[2].x,ra[2].y),
                     packh2(ra[0].z,ra[0].w), packh2(ra[2].z,ra[2].w) };
        uint4 u1 = { packh2(ra[1].x,ra[1].y), packh2(ra[3].x,ra[3].y),
                     packh2(ra[1].z,ra[1].w), packh2(ra[3].z,ra[3].w) };
        unsigned* p = &As[buf*128*ST + r*ST + at*8];
        *(uint4*)(p + (sw?4:0)) = sw ? u1 : u0;
        *(uint4*)(p + (sw?0:4)) = sw ? u0 : u1;
        uint4 v0 = { packh2(rb[0].x,rb[0].y), packh2(rb[2].x,rb[2].y),
                     packh2(rb[0].z,rb[0].w), packh2(rb[2].z,rb[2].w) };
        uint4 v1 = { packh2(rb[1].x,rb[1].y), packh2(rb[3].x,rb[3].y),
                     packh2(rb[1].z,rb[1].w), packh2(rb[3].z,rb[3].w) };
        unsigned* q = &Bs[buf*128*ST + r*ST + at*8];
        *(uint4*)(q + (sw?4:0)) = sw ? v1 : v0;
        *(uint4*)(q + (sw?0:4)) = sw ? v0 : v1;
    };
    auto compute = [&](int buf){
        const int p = lane >> 2;
        #pragma unroll
        for (int ks = 0; ks < 2; ++ks){
            const int col = ks*8 + 2*(lane&3);
            unsigned af[4][4], bf[4][2];
            #pragma unroll
            for (int mi = 0; mi < 4; ++mi){
                int m = wm*64 + mi*16 + p;
                uint2 u0 = *(const uint2*)&As[buf*128*ST +  m   *ST + col];
                uint2 u1 = *(const uint2*)&As[buf*128*ST + (m+8)*ST + col];
                af[mi][0] = u0.x; af[mi][1] = u1.x; af[mi][2] = u0.y; af[mi][3] = u1.y;
            }
            #pragma unroll
            for (int ni = 0; ni < 4; ++ni){
                int n = wn*32 + ni*8 + p;
                uint2 ub = *(const uint2*)&Bs[buf*128*ST + n*ST + col];
                bf[ni][0] = ub.x; bf[ni][1] = ub.y;
            }
            #pragma unroll
            for (int mi = 0; mi < 4; ++mi)
                #pragma unroll
                for (int ni = 0; ni < 4; ++ni)
                    mma16f16(acc[mi][ni], af[mi], bf[ni][0], bf[ni][1]);
        }
    };

    ldtiles(0); sttiles(0); __syncthreads();
    const int nk = K/32;
    for (int t = 1; t < nk; ++t){
        ldtiles(t*32);
        compute((t-1)&1);
        sttiles(t&1);
        __syncthreads();
    }
    compute((nk-1)&1);

    #pragma unroll
    for (int mi = 0; mi < 4; ++mi){
        #pragma unroll
        for (int ni = 0; ni < 4; ++ni){
            int m = m0 + wm*64 + mi*16 + (lane>>2);
            int n = n0 + wn*32 + ni*8 + 2*(lane&3);
            float v0 = acc[mi][ni][0], v1 = acc[mi][ni][1];
            float v2 = acc[mi][ni][2], v3 = acc[mi][ni][3];
            float b0 = bias[n], b1 = bias[n+1];
            v0 = (v0+b0)*scale; v1 = (v1+b1)*scale;
            v2 = (v2+b0)*scale; v3 = (v3+b1)*scale;
            if (permOut){
                int W  = n >> 1;
                int pw = (W & ~7) | ((W&3)<<1) | ((W>>2)&1);
                *(unsigned*)&Ch[(long)m    *ldc + 2*pw] = packh2(v0, v1);
                *(unsigned*)&Ch[(long)(m+8)*ldc + 2*pw] = packh2(v2, v3);
            } else {
                *(float2*)(C + (long)m    *ldc + n) = make_float2(v0, v1);
                *(float2*)(C + (long)(m+8)*ldc + n) = make_float2(v2, v3);
            }
        }
    }
}

// Merged Q/K/V projections. Q scaled by 0.125*log2e. Q,K -> fp16 permuted.
__global__ __launch_bounds__(256)
void qkv_proj(const float* __restrict__ q, const float* __restrict__ k, const float* __restrict__ v,
              const float* __restrict__ qw, const float* __restrict__ qb,
              const float* __restrict__ kw, const float* __restrict__ kb,
              const float* __restrict__ vw, const float* __restrict__ vb,
              __half* __restrict__ qph, __half* __restrict__ kph, float* __restrict__ vp)
{
    extern __shared__ __align__(16) unsigned GSM[];
    const int z = blockIdx.z;
    const float* A  = (z==0)? q  : (z==1)? k  : v;
    const float* W  = (z==0)? qw : (z==1)? kw : vw;
    const float* bi = (z==0)? qb : (z==1)? kb : vb;
    __half* Ch = (z==0)? qph : kph;
    const float scale = (z==0)? 0.125f*LOG2E : 1.0f;
    gemm_body(A, EMB, W, EMB, vp, Ch, EMB, bi, scale, EMB,
              blockIdx.y*128, blockIdx.x*128, z<2, GSM);
}

__global__ __launch_bounds__(256)
void out_proj(const float* __restrict__ A, const float* __restrict__ W,
              const float* __restrict__ bi, float* __restrict__ C)
{
    extern __shared__ __align__(16) unsigned GSM[];
    gemm_body(A, EMB, W, EMB, C, nullptr, EMB, bi, 1.0f, EMB,
              blockIdx.y*128, blockIdx.x*128, false, GSM);
}

// ---------------------------------------------------------------------------
// V transpose+convert: vp fp32 -> vh half [hb*64+d][s].
// ---------------------------------------------------------------------------
__global__ __launch_bounds__(256)
void v_transpose(const float* __restrict__ vp, unsigned* __restrict__ vh2)
{
    __shared__ float T[64][65];
    const int tid = threadIdx.x;
    const int hb = blockIdx.y, h = hb&15, b = hb>>4;
    const int s0 = blockIdx.x*64;

    #pragma unroll
    for (int i = 0; i < 4; ++i){
        int idx = tid + i*256;
        int si = idx>>4, d4 = (idx&15)*4;
        float4 u = *(const float4*)(vp + (long)((s0+si)*2 + b)*EMB + h*64 + d4);
        T[si][d4+0]=u.x; T[si][d4+1]=u.y; T[si][d4+2]=u.z; T[si][d4+3]=u.w;
    }
    __syncthreads();

    #pragma unroll
    for (int j = 0; j < 8; ++j){
        int w = tid + j*256;
        int d = w>>5, sp = w&31;
        unsigned val = packh2(T[2*sp][d], T[2*sp+1][d]);
        vh2[(long)(hb*64 + d)*1024 + (s0>>1) + sp] = val;
    }
}

// ---------------------------------------------------------------------------
// Flash attention (round-15 exact): q-tile 128, 4 warps (MI=2), k-tiles 32
// double-buffered. fp16 QK^T (log2-domain scores) + fp16 PV.
// ---------------------------------------------------------------------------
__global__ __launch_bounds__(128)
void flash_attn(const __half* __restrict__ qp, const __half* __restrict__ kp,
                const __half* __restrict__ vh, float* __restrict__ op,
                float* __restrict__ gm, float* __restrict__ gl)
{
    __shared__ __align__(16) unsigned SU[5120];
    const int tid = threadIdx.x, lane = tid&31, w = tid>>5;
    const int hb = blockIdx.x, h = hb&15, b = hb>>4;
    const int q0 = blockIdx.y*128;
    const long baseh = (long)b*EMB + h*DH;
    const __half* Qg = qp + baseh + (long)q0*(BSZ*EMB);
    const __half* Kg = kp + baseh;
    const __half* Vgh = vh + (long)hb*64*2048;

    for (int i = tid; i < 1024; i += 128){
        int r = i>>3, c = i&7;
        cpa16(&SU[r*40 + c*4], Qg + (long)r*(BSZ*EMB) + c*8);
    }
    asm volatile("cp.async.commit_group;\n");
    asm volatile("cp.async.wait_group 0;\n");
    __syncthreads();

    unsigned Qa[4][2][4];
    {
        const int p = lane>>2, q2 = 2*(lane&3);
        #pragma unroll
        for (int ks = 0; ks < 4; ++ks)
            #pragma unroll
            for (int mi = 0; mi < 2; ++mi){
                int m = w*32 + mi*16 + p;
                int col = ks*8 + q2;
                uint2 u0 = *(const uint2*)&SU[ m   *40 + col];
                uint2 u1 = *(const uint2*)&SU[(m+8)*40 + col];
                Qa[ks][mi][0] = u0.x; Qa[ks][mi][1] = u1.x;
                Qa[ks][mi][2] = u0.y; Qa[ks][mi][3] = u1.y;
            }
    }
    __syncthreads();

    unsigned* const Kb0 = SU;
    unsigned* const Kb1 = SU + 1280;
    unsigned* const Vh0 = SU + 2560;
    unsigned* const Vh1 = SU + 3840;

    auto load_kv = [&](int kt, int sel){
        unsigned* Kb = sel ? Kb1 : Kb0;
        unsigned* Vb = sel ? Vh1 : Vh0;
        const long r0 = (long)kt*32;
        #pragma unroll
        for (int j = 0; j < 2; ++j){
            int idx = tid + j*128;
            int r = idx>>3, c = idx&7;
            cpa16(&Kb[r*40 + c*4], Kg + (r0+r)*(BSZ*EMB) + c*8);
        }
        #pragma unroll
        for (int j = 0; j < 2; ++j){
            int u = tid + j*128;
            int d = u>>2, qc = u&3;
            cpa16(&Vb[d*20 + qc*4], Vgh + (long)d*2048 + kt*32 + qc*8);
        }
    };

    float m_[2][2] = {{-1e30f,-1e30f},{-1e30f,-1e30f}};
    float l_[2][2] = {};
    float o[2][8][4] = {};

    load_kv(0, 0);
    asm volatile("cp.async.commit_group;\n");

    for (int t = 0; t < 64; ++t){
        if (t < 63){
            load_kv(t+1, (t+1)&1);
            asm volatile("cp.async.commit_group;\n");
            asm volatile("cp.async.wait_group 1;\n");
        } else {
            asm volatile("cp.async.wait_group 0;\n");
        }
        __syncthreads();

        unsigned* Kb = (t&1) ? Kb1 : Kb0;
        unsigned* Vb = (t&1) ? Vh1 : Vh0;

        float c_[2][4][4] = {};
        #pragma unroll
        for (int ks = 0; ks < 4; ++ks){
            const int col = ks*8 + 2*(lane&3);
            unsigned bf[4][2];
            #pragma unroll
            for (int ni = 0; ni < 4; ++ni){
                int n = ni*8 + (lane>>2);
                uint2 u = *(const uint2*)&Kb[n*40 + col];
                bf[ni][0] = u.x; bf[ni][1] = u.y;
            }
            #pragma unroll
            for (int mi = 0; mi < 2; ++mi)
                #pragma unroll
                for (int ni = 0; ni < 4; ++ni)
                    mma16f16(c_[mi][ni], Qa[ks][mi], bf[ni][0], bf[ni][1]);
        }

        // online softmax (log2-domain) with rescale-skip
        #pragma unroll
        for (int mi = 0; mi < 2; ++mi){
            float mx0 = -1e30f, mx1 = -1e30f;
            #pragma unroll
            for (int ni = 0; ni < 4; ++ni){
                mx0 = fmaxf(mx0, fmaxf(c_[mi][ni][0], c_[mi][ni][1]));
                mx1 = fmaxf(mx1, fmaxf(c_[mi][ni][2], c_[mi][ni][3]));
            }
            mx0 = fmaxf(mx0, __shfl_xor_sync(0xffffffffu, mx0, 1));
            mx0 = fmaxf(mx0, __shfl_xor_sync(0xffffffffu, mx0, 2));
            mx1 = fmaxf(mx1, __shfl_xor_sync(0xffffffffu, mx1, 1));
            mx1 = fmaxf(mx1, __shfl_xor_sync(0xffffffffu, mx1, 2));
            float mn0 = fmaxf(m_[mi][0], mx0), mn1 = fmaxf(m_[mi][1], mx1);
            if (!__all_sync(0xffffffffu, (mn0 == m_[mi][0]) & (mn1 == m_[mi][1]))){
                float f0 = exp2f(m_[mi][0] - mn0), f1 = exp2f(m_[mi][1] - mn1);
                l_[mi][0] *= f0; l_[mi][1] *= f1;
                #pragma unroll
                for (int ni = 0; ni < 8; ++ni){
                    o[mi][ni][0]*=f0; o[mi][ni][1]*=f0;
                    o[mi][ni][2]*=f1; o[mi][ni][3]*=f1;
                }
                m_[mi][0] = mn0; m_[mi][1] = mn1;
            }
            float s0 = 0.f, s1 = 0.f;
            #pragma unroll
            for (int ni = 0; ni < 4; ++ni){
                c_[mi][ni][0] = exp2f(c_[mi][ni][0]-m_[mi][0]);
                c_[mi][ni][1] = exp2f(c_[mi][ni][1]-m_[mi][0]);
                c_[mi][ni][2] = exp2f(c_[mi][ni][2]-m_[mi][1]);
                c_[mi][ni][3] = exp2f(c_[mi][ni][3]-m_[mi][1]);
                s0 += c_[mi][ni][0]+c_[mi][ni][1];
                s1 += c_[mi][ni][2]+c_[mi][ni][3];
            }
            s0 += __shfl_xor_sync(0xffffffffu, s0, 1);
            s0 += __shfl_xor_sync(0xffffffffu, s0, 2);
            s1 += __shfl_xor_sync(0xffffffffu, s1, 1);
            s1 += __shfl_xor_sync(0xffffffffu, s1, 2);
            l_[mi][0] += s0; l_[mi][1] += s1;
        }

        // P @ V fp16 (no shuffles)
        #pragma unroll
        for (int j = 0; j < 2; ++j){
            unsigned a[2][4];
            #pragma unroll
            for (int mi = 0; mi < 2; ++mi){
                a[mi][0] = packh2(c_[mi][2*j  ][0], c_[mi][2*j  ][1]);
                a[mi][1] = packh2(c_[mi][2*j  ][2], c_[mi][2*j  ][3]);
                a[mi][2] = packh2(c_[mi][2*j+1][0], c_[mi][2*j+1][1]);
                a[mi][3] = packh2(c_[mi][2*j+1][2], c_[mi][2*j+1][3]);
            }
            #pragma unroll
            for (int ni = 0; ni < 8; ++ni){
                int n = ni*8 + (lane>>2);
                unsigned b0 = Vb[n*20 + 8*j + (lane&3)];
                unsigned b1 = Vb[n*20 + 8*j + (lane&3) + 4];
                mma16f16(o[0][ni], a[0], b0, b1);
                mma16f16(o[1][ni], a[1], b0, b1);
            }
        }
        __syncthreads();
    }

    float* Og = op + baseh + (long)q0*(BSZ*EMB);
    #pragma unroll
    for (int mi = 0; mi < 2; ++mi){
        float inv0 = 1.f/l_[mi][0], inv1 = 1.f/l_[mi][1];
        int m = w*32 + mi*16 + (lane>>2);
        #pragma unroll
        for (int ni = 0; ni < 8; ++ni){
            int d = ni*8 + 2*(lane&3);
            *(float2*)(Og + (long)m    *(BSZ*EMB) + d) = make_float2(o[mi][ni][0]*inv0, o[mi][ni][1]*inv0);
            *(float2*)(Og + (long)(m+8)*(BSZ*EMB) + d) = make_float2(o[mi][ni][2]*inv1, o[mi][ni][3]*inv1);
        }
        if ((lane & 3) == 0){
            gm[(long)hb*S_LEN + q0 + m]     = m_[mi][0];
            gm[(long)hb*S_LEN + q0 + m + 8] = m_[mi][1];
            gl[(long)hb*S_LEN + q0 + m]     = l_[mi][0];
            gl[(long)hb*S_LEN + q0 + m + 8] = l_[mi][1];
        }
    }
}

// ---------------------------------------------------------------------------
// attn_avg (round-15 exact): 256 thr, q-tile 128, k-tile 64, warps 4x2
// (MI=2, NI=4), double-buffered heads, fp16 scores, log2-domain exp2.
// ---------------------------------------------------------------------------
__global__ __launch_bounds__(256)
void avg_attn(const __half* __restrict__ qp, const __half* __restrict__ kp,
              const float* __restrict__ gm, const float* __restrict__ gl,
              float* __restrict__ avg)
{
    extern __shared__ __align__(16) unsigned ASH[];
    constexpr int BUF = 128*40 + 64*40;
    const int tid = threadIdx.x, lane = tid&31, wid = tid>>5;
    const int wq = wid>>1, wk = wid&1;
    const int k0 = blockIdx.x*64, q0 = blockIdx.y*128, b = blockIdx.z;
    const int p = lane>>2;

    auto stage = [&](int h, int sel){
        unsigned* Qs = ASH + sel*BUF;
        unsigned* Ks = Qs + 128*40;
        const long baseh = (long)b*EMB + h*DH;
        #pragma unroll
        for (int j = 0; j < 4; ++j){
            int idx = tid + j*256;
            int r = idx>>3, c = idx&7;
            cpa16(&Qs[r*40 + c*4], qp + baseh + (long)(q0+r)*(BSZ*EMB) + c*8);
        }
        #pragma unroll
        for (int j = 0; j < 2; ++j){
            int idx = tid + j*256;
            int r = idx>>3, c = idx&7;
            cpa16(&Ks[r*40 + c*4], kp + baseh + (long)(k0+r)*(BSZ*EMB) + c*8);
        }
        asm volatile("cp.async.commit_group;\n");
    };

    float acc[2][4][4] = {};

    stage(0, 0);
    for (int h = 0; h < NH; ++h){
        if (h < NH-1){
            stage(h+1, (h+1)&1);
            asm volatile("cp.async.wait_group 1;\n");
        } else {
            asm volatile("cp.async.wait_group 0;\n");
        }
        __syncthreads();

        unsigned* Qs = ASH + (h&1)*BUF;
        unsigned* Ks = Qs + 128*40;

        float c_[2][4][4] = {};
        #pragma unroll
        for (int ks = 0; ks < 4; ++ks){
            const int col = ks*8 + 2*(lane&3);
            unsigned a[2][4];
            #pragma unroll
            for (int mi = 0; mi < 2; ++mi){
                int m = wq*32 + mi*16 + p;
                uint2 u0 = *(const uint2*)&Qs[ m   *40 + col];
                uint2 u1 = *(const uint2*)&Qs[(m+8)*40 + col];
                a[mi][0] = u0.x; a[mi][1] = u1.x; a[mi][2] = u0.y; a[mi][3] = u1.y;
            }
            #pragma unroll
            for (int ni = 0; ni < 4; ++ni){
                int n = wk*32 + ni*8 + p;
                uint2 ub = *(const uint2*)&Ks[n*40 + col];
                mma16f16(c_[0][ni], a[0], ub.x, ub.y);
                mma16f16(c_[1][ni], a[1], ub.x, ub.y);
            }
        }

        const int hb = b*NH + h;
        #pragma unroll
        for (int mi = 0; mi < 2; ++mi){
            int r0 = q0 + wq*32 + mi*16 + p;
            float e0 = gm[(long)hb*S_LEN + r0    ] + __log2f(gl[(long)hb*S_LEN + r0    ]) + 4.0f;
            float e1 = gm[(long)hb*S_LEN + r0 + 8] + __log2f(gl[(long)hb*S_LEN + r0 + 8]) + 4.0f;
            #pragma unroll
            for (int ni = 0; ni < 4; ++ni){
                acc[mi][ni][0] += exp2f(c_[mi][ni][0] - e0);
                acc[mi][ni][1] += exp2f(c_[mi][ni][1] - e0);
                acc[mi][ni][2] += exp2f(c_[mi][ni][2] - e1);
                acc[mi][ni][3] += exp2f(c_[mi][ni][3] - e1);
            }
        }
        __syncthreads();
    }

    float* out = avg + (long)b*S2;
    #pragma unroll
    for (int mi = 0; mi < 2; ++mi){
        int r0 = q0 + wq*32 + mi*16 + p;
        #pragma unroll
        for (int ni = 0; ni < 4; ++ni){
            int kc = k0 + wk*32 + ni*8 + 2*(lane&3);
            *(float2*)(out + (long)r0    *S_LEN + kc) = make_float2(acc[mi][ni][0], acc[mi][ni][1]);
            *(float2*)(out + (long)(r0+8)*S_LEN + kc) = make_float2(acc[mi][ni][2], acc[mi][ni][3]);
        }
    }
}

// ---------------------------------------------------------------------------
extern "C" void kernel_launch(void* const* d_in, const int* in_sizes, int n_in,
                              void* d_out, int out_size)
{
    const float* query = (const float*)d_in[0];
    const float* key   = (const float*)d_in[1];
    const float* value = (const float*)d_in[2];
    const float* q_w = (const float*)d_in[3];
    const float* q_b = (const float*)d_in[4];
    const float* k_w = (const float*)d_in[5];
    const float* k_b = (const float*)d_in[6];
    const float* v_w = (const float*)d_in[7];
    const float* v_b = (const float*)d_in[8];
    const float* out_w = (const float*)d_in[9];
    const float* out_b = (const float*)d_in[10];

    float *vp, *op, *gm, *gl;
    __half *qph, *kph, *vh;
    cudaGetSymbolAddress((void**)&qph, g_Qph);
    cudaGetSymbolAddress((void**)&kph, g_Kph);
    cudaGetSymbolAddress((void**)&vp,  g_Vp);
    cudaGetSymbolAddress((void**)&vh,  g_Vh);
    cudaGetSymbolAddress((void**)&op,  g_O);
    cudaGetSymbolAddress((void**)&gm,  g_m);
    cudaGetSymbolAddress((void**)&gl,  g_l);

    float* Z = (float*)d_out;
    float* attn_avg = (float*)d_out + (long)MROWS*EMB;

    static cudaStream_t s2 = nullptr;
    static cudaEvent_t evFork = nullptr, evJoin = nullptr;
    if (!s2){
        cudaStreamCreateWithFlags(&s2, cudaStreamNonBlocking);
        cudaEventCreateWithFlags(&evFork, cudaEventDisableTiming);
        cudaEventCreateWithFlags(&evJoin, cudaEventDisableTiming);
        cudaFuncSetAttribute(avg_attn,  cudaFuncAttributeMaxDynamicSharedMemorySize, 61440);
        cudaFuncSetAttribute(qkv_proj,  cudaFuncAttributeMaxDynamicSharedMemorySize, 49152);
        cudaFuncSetAttribute(out_proj,  cudaFuncAttributeMaxDynamicSharedMemorySize, 49152);
    }

    // 1) Q/K/V projections (fp16 MMA; Q,K -> fp16 permuted; Q log2-domain)
    dim3 gqkv(EMB/128, MROWS/128, 3);
    qkv_proj<<<gqkv, 256, 49152>>>(query, key, value, q_w, q_b, k_w, k_b, v_w, v_b, qph, kph, vp);

    // 1b) V -> fp16 transposed
    dim3 gvt(S_LEN/64, NHEADS, 1);
    v_transpose<<<gvt, 256>>>(vp, (unsigned*)vh);

    // 2) Flash attention (fp16 scores + fp16 PV)
    dim3 gfa(NHEADS, S_LEN/128, 1);
    flash_attn<<<gfa, 128>>>(qph, kph, vh, op, gm, gl);

    // fork: out_proj concurrent with avg_attn
    cudaEventRecord(evFork, 0);
    cudaStreamWaitEvent(s2, evFork, 0);

    dim3 gop(EMB/128, MROWS/128, 1);
    out_proj<<<gop, 256, 49152, s2>>>(op, out_w, out_b, Z);
    cudaEventRecord(evJoin, s2);

    dim3 gav(S_LEN/64, S_LEN/128, BSZ);
    avg_attn<<<gav, 256, 61440>>>(qph, kph, gm, gl, attn_avg);

    cudaStreamWaitEvent(0, evJoin, 0);
}

// round 17
// speedup vs baseline: 1.9594x; 1.3087x over previous
#include <cuda_runtime.h>
#include <cuda_fp16.h>

#define S_LEN 2048
#define BSZ   2
#define EMB   1024
#define NH    16
#define DH    64
#define MROWS 4096
#define NHEADS 32
#define S2 ((long)S_LEN*S_LEN)
#define LOG2E 1.4426950408889634f

// Scratch (__device__ globals per alloc-free rule)
__device__ __half g_H16[16777216];          // fp16 pair-permuted: q,k,v inputs (3x4M) + qw,kw,vw,ow (4x1M)
__device__ __half g_Qph[(size_t)MROWS*EMB]; // fp16 permuted, pre-scaled 0.125*log2e
__device__ __half g_Kph[(size_t)MROWS*EMB]; // fp16 permuted
__device__ float  g_Vp [MROWS*EMB];         // fp32 (v_transpose input)
__device__ __half g_Vh [(size_t)MROWS*EMB]; // transposed fp16: row (hb*64+d), col s
__device__ __half g_Oh [(size_t)MROWS*EMB]; // flash output, fp16 permuted
__device__ float  g_m  [NHEADS*S_LEN];
__device__ float  g_l  [NHEADS*S_LEN];

__device__ __forceinline__ unsigned packh2(float lo, float hi){
    __half2 h = __floats2half2_rn(lo, hi);
    return *(unsigned*)&h;
}
__device__ __forceinline__ void mma16f16(float* c, const unsigned* a, unsigned b0, unsigned b1){
    asm volatile("mma.sync.aligned.m16n8k16.row.col.f32.f16.f16.f32 "
      "{%0,%1,%2,%3}, {%4,%5,%6,%7}, {%8,%9}, {%0,%1,%2,%3};\n"
      : "+f"(c[0]), "+f"(c[1]), "+f"(c[2]), "+f"(c[3])
      : "r"(a[0]), "r"(a[1]), "r"(a[2]), "r"(a[3]), "r"(b0), "r"(b1));
}
__device__ __forceinline__ void cpa16(void* dst, const void* src){
    unsigned d = (unsigned)__cvta_generic_to_shared(dst);
    asm volatile("cp.async.cg.shared.global [%0], [%1], 16;\n" :: "r"(d), "l"(src));
}

// ---------------------------------------------------------------------------
// prep: fp32 -> fp16 pair-permuted ([W0,W4,W1,W5,W2,W6,W3,W7] per 16-half
// group). 1M groups (16M elems): inputs q,k,v then weights qw,kw,vw,ow.
// ---------------------------------------------------------------------------
__global__ __launch_bounds__(256)
void prep_convert(const float* __restrict__ q, const float* __restrict__ k,
                  const float* __restrict__ v, const float* __restrict__ qw,
                  const float* __restrict__ kw, const float* __restrict__ vw,
                  const float* __restrict__ ow, __half* __restrict__ dst)
{
    long g = (long)blockIdx.x*256 + threadIdx.x;   // group index (16 halves each)
    const float* src; long base, off;
    if (g < 786432){                                // 3 inputs x 262144 groups
        int t = (int)(g / 262144); off = (g % 262144)*16;
        src = (t==0)? q : (t==1)? k : v; base = (long)t*4194304;
    } else {
        long g2 = g - 786432; int t = (int)(g2 / 65536); off = (g2 % 65536)*16;
        src = (t==0)? qw : (t==1)? kw : (t==2)? vw : ow;
        base = 12582912 + (long)t*1048576;
    }
    float4 f0 = *(const float4*)(src+off),   f1 = *(const float4*)(src+off+4);
    float4 f2 = *(const float4*)(src+off+8), f3 = *(const float4*)(src+off+12);
    uint4 u0 = { packh2(f0.x,f0.y), packh2(f2.x,f2.y), packh2(f0.z,f0.w), packh2(f2.z,f2.w) };
    uint4 u1 = { packh2(f1.x,f1.y), packh2(f3.x,f3.y), packh2(f1.z,f1.w), packh2(f3.z,f3.w) };
    *(uint4*)(dst + base + off)     = u0;
    *(uint4*)(dst + base + off + 8) = u1;
}

// ---------------------------------------------------------------------------
// TN fp16 GEMM v5: BM=128, BN=128, BK=64, WM=64 (MI=4), WN=32 (NI=4), 8 warps.
// Operands are fp16 pair-permuted in GLOBAL -> staging is pure cp.async
// (rows of 32 words, stride 40 — proven conflict-free flash pattern).
// Dynamic smem: 2 ops x 2 bufs x 128 x 40 x 4 = 81920 B.
// permOut: write fp16 pair-permuted into Ch.
// ---------------------------------------------------------------------------
__device__ __forceinline__
void gemm_body(const __half* __restrict__ A, int lda,
               const __half* __restrict__ B, int ldb,
               float* __restrict__ C, __half* __restrict__ Ch, int ldc,
               const float* __restrict__ bias, float scale, int K,
               int m0, int n0, bool permOut, unsigned* SM)
{
    constexpr int ST = 40;
    unsigned* const As = SM;             // [2][128][40]
    unsigned* const Bs = SM + 2*128*ST;  // [2][128][40]

    const int tid  = threadIdx.x;
    const int lane = tid & 31, wid = tid >> 5;
    const int wm = wid >> 2, wn = wid & 3;

    float acc[4][4][4] = {};

    auto stage = [&](int t, int buf){
        #pragma unroll
        for (int j = 0; j < 4; ++j){
            int idx = tid + j*256;       // 1024 chunks: 128 rows x 8
            int r = idx>>3, ch = idx&7;
            cpa16(&As[buf*128*ST + r*ST + ch*4], A + (long)(m0+r)*lda + t*64 + ch*8);
        }
        #pragma unroll
        for (int j = 0; j < 4; ++j){
            int idx = tid + j*256;
            int r = idx>>3, ch = idx&7;
            cpa16(&Bs[buf*128*ST + r*ST + ch*4], B + (long)(n0+r)*ldb + t*64 + ch*8);
        }
    };
    auto compute = [&](int buf){
        const int p = lane >> 2;
        #pragma unroll
        for (int ks = 0; ks < 4; ++ks){
            const int col = ks*8 + 2*(lane&3);
            unsigned af[4][4], bf[4][2];
            #pragma unroll
            for (int mi = 0; mi < 4; ++mi){
                int m = wm*64 + mi*16 + p;
                uint2 u0 = *(const uint2*)&As[buf*128*ST +  m   *ST + col];
                uint2 u1 = *(const uint2*)&As[buf*128*ST + (m+8)*ST + col];
                af[mi][0] = u0.x; af[mi][1] = u1.x; af[mi][2] = u0.y; af[mi][3] = u1.y;
            }
            #pragma unroll
            for (int ni = 0; ni < 4; ++ni){
                int n = wn*32 + ni*8 + p;
                uint2 ub = *(const uint2*)&Bs[buf*128*ST + n*ST + col];
                bf[ni][0] = ub.x; bf[ni][1] = ub.y;
            }
            #pragma unroll
            for (int mi = 0; mi < 4; ++mi)
                #pragma unroll
                for (int ni = 0; ni < 4; ++ni)
                    mma16f16(acc[mi][ni], af[mi], bf[ni][0], bf[ni][1]);
        }
    };

    const int nk = K/64;
    stage(0, 0);
    asm volatile("cp.async.commit_group;\n");
    for (int t = 0; t < nk; ++t){
        if (t < nk-1){
            stage(t+1, (t+1)&1);
            asm volatile("cp.async.commit_group;\n");
            asm volatile("cp.async.wait_group 1;\n");
        } else {
            asm volatile("cp.async.wait_group 0;\n");
        }
        __syncthreads();
        compute(t&1);
        __syncthreads();
    }

    #pragma unroll
    for (int mi = 0; mi < 4; ++mi){
        #pragma unroll
        for (int ni = 0; ni < 4; ++ni){
            int m = m0 + wm*64 + mi*16 + (lane>>2);
            int n = n0 + wn*32 + ni*8 + 2*(lane&3);
            float v0 = acc[mi][ni][0], v1 = acc[mi][ni][1];
            float v2 = acc[mi][ni][2], v3 = acc[mi][ni][3];
            float b0 = bias[n], b1 = bias[n+1];
            v0 = (v0+b0)*scale; v1 = (v1+b1)*scale;
            v2 = (v2+b0)*scale; v3 = (v3+b1)*scale;
            if (permOut){
                int W  = n >> 1;
                int pw = (W & ~7) | ((W&3)<<1) | ((W>>2)&1);
                *(unsigned*)&Ch[(long)m    *ldc + 2*pw] = packh2(v0, v1);
                *(unsigned*)&Ch[(long)(m+8)*ldc + 2*pw] = packh2(v2, v3);
            } else {
                *(float2*)(C + (long)m    *ldc + n) = make_float2(v0, v1);
                *(float2*)(C + (long)(m+8)*ldc + n) = make_float2(v2, v3);
            }
        }
    }
}

// Merged Q/K/V projections (fp16 operands from g_H16).
__global__ __launch_bounds__(256)
void qkv_proj(const __half* __restrict__ H,
              const float* __restrict__ qb, const float* __restrict__ kb,
              const float* __restrict__ vb,
              __half* __restrict__ qph, __half* __restrict__ kph, float* __restrict__ vp)
{
    extern __shared__ __align__(16) unsigned GSM[];
    const int z = blockIdx.z;
    const __half* A  = H + (long)z*4194304;
    const __half* W  = H + 12582912 + (long)z*1048576;
    const float*  bi = (z==0)? qb : (z==1)? kb : vb;
    __half* Ch = (z==0)? qph : kph;
    const float scale = (z==0)? 0.125f*LOG2E : 1.0f;
    gemm_body(A, EMB, W, EMB, vp, Ch, EMB, bi, scale, EMB,
              blockIdx.y*128, blockIdx.x*128, z<2, GSM);
}

__global__ __launch_bounds__(256)
void out_proj(const __half* __restrict__ A, const __half* __restrict__ W,
              const float* __restrict__ bi, float* __restrict__ C)
{
    extern __shared__ __align__(16) unsigned GSM[];
    gemm_body(A, EMB, W, EMB, C, nullptr, EMB, bi, 1.0f, EMB,
              blockIdx.y*128, blockIdx.x*128, false, GSM);
}

// ---------------------------------------------------------------------------
// V transpose+convert: vp fp32 -> vh half [hb*64+d][s].
// ---------------------------------------------------------------------------
__global__ __launch_bounds__(256)
void v_transpose(const float* __restrict__ vp, unsigned* __restrict__ vh2)
{
    __shared__ float T[64][65];
    const int tid = threadIdx.x;
    const int hb = blockIdx.y, h = hb&15, b = hb>>4;
    const int s0 = blockIdx.x*64;

    #pragma unroll
    for (int i = 0; i < 4; ++i){
        int idx = tid + i*256;
        int si = idx>>4, d4 = (idx&15)*4;
        float4 u = *(const float4*)(vp + (long)((s0+si)*2 + b)*EMB + h*64 + d4);
        T[si][d4+0]=u.x; T[si][d4+1]=u.y; T[si][d4+2]=u.z; T[si][d4+3]=u.w;
    }
    __syncthreads();

    #pragma unroll
    for (int j = 0; j < 8; ++j){
        int w = tid + j*256;
        int d = w>>5, sp = w&31;
        unsigned val = packh2(T[2*sp][d], T[2*sp+1][d]);
        vh2[(long)(hb*64 + d)*1024 + (s0>>1) + sp] = val;
    }
}

// ---------------------------------------------------------------------------
// Flash attention: q-tile 128, 4 warps (MI=2), k-tiles 32 double-buffered.
// fp16 QK^T (log2-domain scores) + fp16 PV. Output O -> fp16 permuted (g_Oh).
// ---------------------------------------------------------------------------
__global__ __launch_bounds__(128)
void flash_attn(const __half* __restrict__ qp, const __half* __restrict__ kp,
                const __half* __restrict__ vh, __half* __restrict__ oh,
                float* __restrict__ gm, float* __restrict__ gl)
{
    __shared__ __align__(16) unsigned SU[5120];
    const int tid = threadIdx.x, lane = tid&31, w = tid>>5;
    const int hb = blockIdx.x, h = hb&15, b = hb>>4;
    const int q0 = blockIdx.y*128;
    const long baseh = (long)b*EMB + h*DH;
    const __half* Qg = qp + baseh + (long)q0*(BSZ*EMB);
    const __half* Kg = kp + baseh;
    const __half* Vgh = vh + (long)hb*64*2048;

    for (int i = tid; i < 1024; i += 128){
        int r = i>>3, c = i&7;
        cpa16(&SU[r*40 + c*4], Qg + (long)r*(BSZ*EMB) + c*8);
    }
    asm volatile("cp.async.commit_group;\n");
    asm volatile("cp.async.wait_group 0;\n");
    __syncthreads();

    unsigned Qa[4][2][4];
    {
        const int p = lane>>2, q2 = 2*(lane&3);
        #pragma unroll
        for (int ks = 0; ks < 4; ++ks)
            #pragma unroll
            for (int mi = 0; mi < 2; ++mi){
                int m = w*32 + mi*16 + p;
                int col = ks*8 + q2;
                uint2 u0 = *(const uint2*)&SU[ m   *40 + col];
                uint2 u1 = *(const uint2*)&SU[(m+8)*40 + col];
                Qa[ks][mi][0] = u0.x; Qa[ks][mi][1] = u1.x;
                Qa[ks][mi][2] = u0.y; Qa[ks][mi][3] = u1.y;
            }
    }
    __syncthreads();

    unsigned* const Kb0 = SU;
    unsigned* const Kb1 = SU + 1280;
    unsigned* const Vh0 = SU + 2560;
    unsigned* const Vh1 = SU + 3840;

    auto load_kv = [&](int kt, int sel){
        unsigned* Kb = sel ? Kb1 : Kb0;
        unsigned* Vb = sel ? Vh1 : Vh0;
        const long r0 = (long)kt*32;
        #pragma unroll
        for (int j = 0; j < 2; ++j){
            int idx = tid + j*128;
            int r = idx>>3, c = idx&7;
            cpa16(&Kb[r*40 + c*4], Kg + (r0+r)*(BSZ*EMB) + c*8);
        }
        #pragma unroll
        for (int j = 0; j < 2; ++j){
            int u = tid + j*128;
            int d = u>>2, qc = u&3;
            cpa16(&Vb[d*20 + qc*4], Vgh + (long)d*2048 + kt*32 + qc*8);
        }
    };

    float m_[2][2] = {{-1e30f,-1e30f},{-1e30f,-1e30f}};
    float l_[2][2] = {};
    float o[2][8][4] = {};

    load_kv(0, 0);
    asm volatile("cp.async.commit_group;\n");

    for (int t = 0; t < 64; ++t){
        if (t < 63){
            load_kv(t+1, (t+1)&1);
            asm volatile("cp.async.commit_group;\n");
            asm volatile("cp.async.wait_group 1;\n");
        } else {
            asm volatile("cp.async.wait_group 0;\n");
        }
        __syncthreads();

        unsigned* Kb = (t&1) ? Kb1 : Kb0;
        unsigned* Vb = (t&1) ? Vh1 : Vh0;

        float c_[2][4][4] = {};
        #pragma unroll
        for (int ks = 0; ks < 4; ++ks){
            const int col = ks*8 + 2*(lane&3);
            unsigned bf[4][2];
            #pragma unroll
            for (int ni = 0; ni < 4; ++ni){
                int n = ni*8 + (lane>>2);
                uint2 u = *(const uint2*)&Kb[n*40 + col];
                bf[ni][0] = u.x; bf[ni][1] = u.y;
            }
            #pragma unroll
            for (int mi = 0; mi < 2; ++mi)
                #pragma unroll
                for (int ni = 0; ni < 4; ++ni)
                    mma16f16(c_[mi][ni], Qa[ks][mi], bf[ni][0], bf[ni][1]);
        }

        // online softmax (log2-domain) with rescale-skip
        #pragma unroll
        for (int mi = 0; mi < 2; ++mi){
            float mx0 = -1e30f, mx1 = -1e30f;
            #pragma unroll
            for (int ni = 0; ni < 4; ++ni){
                mx0 = fmaxf(mx0, fmaxf(c_[mi][ni][0], c_[mi][ni][1]));
                mx1 = fmaxf(mx1, fmaxf(c_[mi][ni][2], c_[mi][ni][3]));
            }
            mx0 = fmaxf(mx0, __shfl_xor_sync(0xffffffffu, mx0, 1));
            mx0 = fmaxf(mx0, __shfl_xor_sync(0xffffffffu, mx0, 2));
            mx1 = fmaxf(mx1, __shfl_xor_sync(0xffffffffu, mx1, 1));
            mx1 = fmaxf(mx1, __shfl_xor_sync(0xffffffffu, mx1, 2));
            float mn0 = fmaxf(m_[mi][0], mx0), mn1 = fmaxf(m_[mi][1], mx1);
            if (!__all_sync(0xffffffffu, (mn0 == m_[mi][0]) & (mn1 == m_[mi][1]))){
                float f0 = exp2f(m_[mi][0] - mn0), f1 = exp2f(m_[mi][1] - mn1);
                l_[mi][0] *= f0; l_[mi][1] *= f1;
                #pragma unroll
                for (int ni = 0; ni < 8; ++ni){
                    o[mi][ni][0]*=f0; o[mi][ni][1]*=f0;
                    o[mi][ni][2]*=f1; o[mi][ni][3]*=f1;
                }
                m_[mi][0] = mn0; m_[mi][1] = mn1;
            }
            float s0 = 0.f, s1 = 0.f;
            #pragma unroll
            for (int ni = 0; ni < 4; ++ni){
                c_[mi][ni][0] = exp2f(c_[mi][ni][0]-m_[mi][0]);
                c_[mi][ni][1] = exp2f(c_[mi][ni][1]-m_[mi][0]);
                c_[mi][ni][2] = exp2f(c_[mi][ni][2]-m_[mi][1]);
                c_[mi][ni][3] = exp2f(c_[mi][ni][3]-m_[mi][1]);
                s0 += c_[mi][ni][0]+c_[mi][ni][1];
                s1 += c_[mi][ni][2]+c_[mi][ni][3];
            }
            s0 += __shfl_xor_sync(0xffffffffu, s0, 1);
            s0 += __shfl_xor_sync(0xffffffffu, s0, 2);
            s1 += __shfl_xor_sync(0xffffffffu, s1, 1);
            s1 += __shfl_xor_sync(0xffffffffu, s1, 2);
            l_[mi][0] += s0; l_[mi][1] += s1;
        }

        // P @ V fp16 (no shuffles)
        #pragma unroll
        for (int j = 0; j < 2; ++j){
            unsigned a[2][4];
            #pragma unroll
            for (int mi = 0; mi < 2; ++mi){
                a[mi][0] = packh2(c_[mi][2*j  ][0], c_[mi][2*j  ][1]);
                a[mi][1] = packh2(c_[mi][2*j  ][2], c_[mi][2*j  ][3]);
                a[mi][2] = packh2(c_[mi][2*j+1][0], c_[mi][2*j+1][1]);
                a[mi][3] = packh2(c_[mi][2*j+1][2], c_[mi][2*j+1][3]);
            }
            #pragma unroll
            for (int ni = 0; ni < 8; ++ni){
                int n = ni*8 + (lane>>2);
                unsigned b0 = Vb[n*20 + 8*j + (lane&3)];
                unsigned b1 = Vb[n*20 + 8*j + (lane&3) + 4];
                mma16f16(o[0][ni], a[0], b0, b1);
                mma16f16(o[1][ni], a[1], b0, b1);
            }
        }
        __syncthreads();
    }

    // epilogue: O -> fp16 pair-permuted (out_proj operand format)
    __half* Ohg = oh + baseh + (long)q0*(BSZ*EMB);
    #pragma unroll
    for (int mi = 0; mi < 2; ++mi){
        float inv0 = 1.f/l_[mi][0], inv1 = 1.f/l_[mi][1];
        int m = w*32 + mi*16 + (lane>>2);
        #pragma unroll
        for (int ni = 0; ni < 8; ++ni){
            int wrd = ni*4 + (lane&3);                       // local word (d>>1)
            int pw  = (wrd & ~7) | ((wrd&3)<<1) | ((wrd>>2)&1);
            *(unsigned*)&Ohg[(long)m    *(BSZ*EMB) + 2*pw] = packh2(o[mi][ni][0]*inv0, o[mi][ni][1]*inv0);
            *(unsigned*)&Ohg[(long)(m+8)*(BSZ*EMB) + 2*pw] = packh2(o[mi][ni][2]*inv1, o[mi][ni][3]*inv1);
        }
        if ((lane & 3) == 0){
            gm[(long)hb*S_LEN + q0 + m]     = m_[mi][0];
            gm[(long)hb*S_LEN + q0 + m + 8] = m_[mi][1];
            gl[(long)hb*S_LEN + q0 + m]     = l_[mi][0];
            gl[(long)hb*S_LEN + q0 + m + 8] = l_[mi][1];
        }
    }
}

// ---------------------------------------------------------------------------
// attn_avg (round-16 exact): 256 thr, q-tile 128, k-tile 64, warps 4x2,
// double-buffered heads, fp16 scores, log2-domain exp2.
// ---------------------------------------------------------------------------
__global__ __launch_bounds__(256)
void avg_attn(const __half* __restrict__ qp, const __half* __restrict__ kp,
              const float* __restrict__ gm, const float* __restrict__ gl,
              float* __restrict__ avg)
{
    extern __shared__ __align__(16) unsigned ASH[];
    constexpr int BUF = 128*40 + 64*40;
    const int tid = threadIdx.x, lane = tid&31, wid = tid>>5;
    const int wq = wid>>1, wk = wid&1;
    const int k0 = blockIdx.x*64, q0 = blockIdx.y*128, b = blockIdx.z;
    const int p = lane>>2;

    auto stage = [&](int h, int sel){
        unsigned* Qs = ASH + sel*BUF;
        unsigned* Ks = Qs + 128*40;
        const long baseh = (long)b*EMB + h*DH;
        #pragma unroll
        for (int j = 0; j < 4; ++j){
            int idx = tid + j*256;
            int r = idx>>3, c = idx&7;
            cpa16(&Qs[r*40 + c*4], qp + baseh + (long)(q0+r)*(BSZ*EMB) + c*8);
        }
        #pragma unroll
        for (int j = 0; j < 2; ++j){
            int idx = tid + j*256;
            int r = idx>>3, c = idx&7;
            cpa16(&Ks[r*40 + c*4], kp + baseh + (long)(k0+r)*(BSZ*EMB) + c*8);
        }
        asm volatile("cp.async.commit_group;\n");
    };

    float acc[2][4][4] = {};

    stage(0, 0);
    for (int h = 0; h < NH; ++h){
        if (h < NH-1){
            stage(h+1, (h+1)&1);
            asm volatile("cp.async.wait_group 1;\n");
        } else {
            asm volatile("cp.async.wait_group 0;\n");
        }
        __syncthreads();

        unsigned* Qs = ASH + (h&1)*BUF;
        unsigned* Ks = Qs + 128*40;

        float c_[2][4][4] = {};
        #pragma unroll
        for (int ks = 0; ks < 4; ++ks){
            const int col = ks*8 + 2*(lane&3);
            unsigned a[2][4];
            #pragma unroll
            for (int mi = 0; mi < 2; ++mi){
                int m = wq*32 + mi*16 + p;
                uint2 u0 = *(const uint2*)&Qs[ m   *40 + col];
                uint2 u1 = *(const uint2*)&Qs[(m+8)*40 + col];
                a[mi][0] = u0.x; a[mi][1] = u1.x; a[mi][2] = u0.y; a[mi][3] = u1.y;
            }
            #pragma unroll
            for (int ni = 0; ni < 4; ++ni){
                int n = wk*32 + ni*8 + p;
                uint2 ub = *(const uint2*)&Ks[n*40 + col];
                mma16f16(c_[0][ni], a[0], ub.x, ub.y);
                mma16f16(c_[1][ni], a[1], ub.x, ub.y);
            }
        }

        const int hb = b*NH + h;
        #pragma unroll
        for (int mi = 0; mi < 2; ++mi){
            int r0 = q0 + wq*32 + mi*16 + p;
            float e0 = gm[(long)hb*S_LEN + r0    ] + __log2f(gl[(long)hb*S_LEN + r0    ]) + 4.0f;
            float e1 = gm[(long)hb*S_LEN + r0 + 8] + __log2f(gl[(long)hb*S_LEN + r0 + 8]) + 4.0f;
            #pragma unroll
            for (int ni = 0; ni < 4; ++ni){
                acc[mi][ni][0] += exp2f(c_[mi][ni][0] - e0);
                acc[mi][ni][1] += exp2f(c_[mi][ni][1] - e0);
                acc[mi][ni][2] += exp2f(c_[mi][ni][2] - e1);
                acc[mi][ni][3] += exp2f(c_[mi][ni][3] - e1);
            }
        }
        __syncthreads();
    }

    float* out = avg + (long)b*S2;
    #pragma unroll
    for (int mi = 0; mi < 2; ++mi){
        int r0 = q0 + wq*32 + mi*16 + p;
        #pragma unroll
        for (int ni = 0; ni < 4; ++ni){
            int kc = k0 + wk*32 + ni*8 + 2*(lane&3);
            *(float2*)(out + (long)r0    *S_LEN + kc) = make_float2(acc[mi][ni][0], acc[mi][ni][1]);
            *(float2*)(out + (long)(r0+8)*S_LEN + kc) = make_float2(acc[mi][ni][2], acc[mi][ni][3]);
        }
    }
}

// ---------------------------------------------------------------------------
extern "C" void kernel_launch(void* const* d_in, const int* in_sizes, int n_in,
                              void* d_out, int out_size)
{
    const float* query = (const float*)d_in[0];
    const float* key   = (const float*)d_in[1];
    const float* value = (const float*)d_in[2];
    const float* q_w = (const float*)d_in[3];
    const float* q_b = (const float*)d_in[4];
    const float* k_w = (const float*)d_in[5];
    const float* k_b = (const float*)d_in[6];
    const float* v_w = (const float*)d_in[7];
    const float* v_b = (const float*)d_in[8];
    const float* out_w = (const float*)d_in[9];
    const float* out_b = (const float*)d_in[10];

    float *vp, *gm, *gl;
    __half *H, *qph, *kph, *vh, *oh;
    cudaGetSymbolAddress((void**)&H,   g_H16);
    cudaGetSymbolAddress((void**)&qph, g_Qph);
    cudaGetSymbolAddress((void**)&kph, g_Kph);
    cudaGetSymbolAddress((void**)&vp,  g_Vp);
    cudaGetSymbolAddress((void**)&vh,  g_Vh);
    cudaGetSymbolAddress((void**)&oh,  g_Oh);
    cudaGetSymbolAddress((void**)&gm,  g_m);
    cudaGetSymbolAddress((void**)&gl,  g_l);

    float* Z = (float*)d_out;
    float* attn_avg = (float*)d_out + (long)MROWS*EMB;

    static cudaStream_t s2 = nullptr;
    static cudaEvent_t evFork = nullptr, evJoin = nullptr;
    if (!s2){
        cudaStreamCreateWithFlags(&s2, cudaStreamNonBlocking);
        cudaEventCreateWithFlags(&evFork, cudaEventDisableTiming);
        cudaEventCreateWithFlags(&evJoin, cudaEventDisableTiming);
        cudaFuncSetAttribute(avg_attn,  cudaFuncAttributeMaxDynamicSharedMemorySize, 61440);
        cudaFuncSetAttribute(qkv_proj,  cudaFuncAttributeMaxDynamicSharedMemorySize, 81920);
        cudaFuncSetAttribute(out_proj,  cudaFuncAttributeMaxDynamicSharedMemorySize, 81920);
    }

    // 0) Convert inputs + weights to fp16 pair-permuted
    prep_convert<<<4096, 256>>>(query, key, value, q_w, k_w, v_w, out_w, H);

    // 1) Q/K/V projections (fp16 cp.async GEMM)
    dim3 gqkv(EMB/128, MROWS/128, 3);
    qkv_proj<<<gqkv, 256, 81920>>>(H, q_b, k_b, v_b, qph, kph, vp);

    // 1b) V -> fp16 transposed
    dim3 gvt(S_LEN/64, NHEADS, 1);
    v_transpose<<<gvt, 256>>>(vp, (unsigned*)vh);

    // 2) Flash attention (O -> fp16 permuted)
    dim3 gfa(NHEADS, S_LEN/128, 1);
    flash_attn<<<gfa, 128>>>(qph, kph, vh, oh, gm, gl);

    // fork: out_proj concurrent with avg_attn
    cudaEventRecord(evFork, 0);
    cudaStreamWaitEvent(s2, evFork, 0);

    dim3 gop(EMB/128, MROWS/128, 1);
    out_proj<<<gop, 256, 81920, s2>>>(oh, H + 12582912 + 3L*1048576, out_b, Z);
    cudaEventRecord(evJoin, s2);

    dim3 gav(S_LEN/64, S_LEN/128, BSZ);
    avg_attn<<<gav, 256, 61440>>>(qph, kph, gm, gl, attn_avg);

    cudaStreamWaitEvent(0, evJoin, 0);
}